// round 12
// baseline (speedup 1.0000x reference)
#include <cuda_runtime.h>
#include <cuda_fp16.h>
#include <math.h>
#include <stdint.h>

#define NN 50000
#define NE 100000
#define D  64
#define F  128
#define DD 4096
#define EPSV 1e-5f
#define ECHUNK 25600
#define NEPAD 100096
#define MBLK 782       // NEPAD / 128
#define GY 37          // 32*37 = 1184 CTAs = 8 waves of 148

// ---------------- scratch (static device globals; no runtime alloc) ----------------
__device__ __align__(16) __half g_raw0[(size_t)ECHUNK * DD];
__device__ __align__(16) __half g_raw1[(size_t)ECHUNK * DD];
__device__ __align__(16) __half g_raw2[(size_t)ECHUNK * DD];
__device__ __align__(16) __half g_raw3[(size_t)ECHUNK * DD];

__device__ __forceinline__ __half* raw_row(int e) {
    int c = e / ECHUNK;
    int r = e - c * ECHUNK;
    __half* base = (c == 0) ? g_raw0 : (c == 1) ? g_raw1 : (c == 2) ? g_raw2 : g_raw3;
    return base + (size_t)r * DD;
}

__device__ __align__(16) __half g_Ah[(size_t)NEPAD * F];   // 25.6 MB
__device__ __align__(16) __half g_Bh[(size_t)F * DD];      // 1 MB  [k][n]

__device__ __align__(16) float g_colsum[DD];
__device__ __align__(16) float g_colsq[DD];
__device__ __align__(16) float g_a[DD];
__device__ __align__(16) float g_c[DD];
__device__ __align__(16) float g_cnt[NN];
__device__ __align__(16) float g_inv[NN];
__device__ __align__(16) float g_agg[NN * D];
__device__ __align__(16) float g_node[NN * D];
__device__ __align__(16) float g_acc[NN * D];

struct alignas(8) H4 { __half2 x, y; };

// ---------------- zero / count helpers ----------------
__global__ void k_zero_pre() {
    int i = blockIdx.x * 256 + threadIdx.x;
    if (i < DD) { g_colsum[i] = 0.f; g_colsq[i] = 0.f; }
    if (i < NN) g_cnt[i] = 0.f;
    if (i < NN * D) g_agg[i] = 0.f;
}

__global__ void k_count(const int* __restrict__ ei) {
    int e = blockIdx.x * 256 + threadIdx.x;
    if (e < NE) atomicAdd(&g_cnt[ei[NE + e]], 1.0f);
}

__global__ void k_inv() {
    int i = blockIdx.x * 256 + threadIdx.x;
    if (i < NN) g_inv[i] = 1.0f / fmaxf(g_cnt[i], 1.0f);
}

// ---------------- fp32 -> fp16 pre-conversion ----------------
__global__ void k_toh_A(const float* __restrict__ A) {
    int i = blockIdx.x * 256 + threadIdx.x;   // one per 8 elems
    if (i >= NEPAD * F / 8) return;
    int r = i / (F / 8);
    H4 h0, h1;
    if (r < NE) {
        const float4* s = reinterpret_cast<const float4*>(A) + (size_t)i * 2;
        float4 v0 = s[0], v1 = s[1];
        h0.x = __floats2half2_rn(v0.x, v0.y); h0.y = __floats2half2_rn(v0.z, v0.w);
        h1.x = __floats2half2_rn(v1.x, v1.y); h1.y = __floats2half2_rn(v1.z, v1.w);
    } else {
        h0.x = h0.y = h1.x = h1.y = __floats2half2_rn(0.f, 0.f);
    }
    H4* d = reinterpret_cast<H4*>(g_Ah) + (size_t)i * 2;
    d[0] = h0; d[1] = h1;
}

__global__ void k_toh_B(const float* __restrict__ B) {
    int i = blockIdx.x * 256 + threadIdx.x;
    if (i >= F * DD / 8) return;
    const float4* s = reinterpret_cast<const float4*>(B) + (size_t)i * 2;
    float4 v0 = s[0], v1 = s[1];
    H4 h0, h1;
    h0.x = __floats2half2_rn(v0.x, v0.y); h0.y = __floats2half2_rn(v0.z, v0.w);
    h1.x = __floats2half2_rn(v1.x, v1.y); h1.y = __floats2half2_rn(v1.z, v1.w);
    H4* d = reinterpret_cast<H4*>(g_Bh) + (size_t)i * 2;
    d[0] = h0; d[1] = h1;
}

// ---------------- tensor-core GEMM helpers ----------------
__device__ __forceinline__ void ldsm_x4(uint32_t& r0, uint32_t& r1, uint32_t& r2, uint32_t& r3,
                                        uint32_t addr) {
    asm volatile("ldmatrix.sync.aligned.m8n8.x4.shared.b16 {%0,%1,%2,%3}, [%4];"
                 : "=r"(r0), "=r"(r1), "=r"(r2), "=r"(r3) : "r"(addr));
}
__device__ __forceinline__ void ldsm_x4_t(uint32_t& r0, uint32_t& r1, uint32_t& r2, uint32_t& r3,
                                          uint32_t addr) {
    asm volatile("ldmatrix.sync.aligned.m8n8.x4.trans.shared.b16 {%0,%1,%2,%3}, [%4];"
                 : "=r"(r0), "=r"(r1), "=r"(r2), "=r"(r3) : "r"(addr));
}
__device__ __forceinline__ void mma16816(float* c, const uint32_t* a, const uint32_t* b) {
    asm volatile(
        "mma.sync.aligned.m16n8k16.row.col.f32.f16.f16.f32 "
        "{%0,%1,%2,%3}, {%4,%5,%6,%7}, {%8,%9}, {%0,%1,%2,%3};"
        : "+f"(c[0]), "+f"(c[1]), "+f"(c[2]), "+f"(c[3])
        : "r"(a[0]), "r"(a[1]), "r"(a[2]), "r"(a[3]), "r"(b[0]), "r"(b[1]));
}
__device__ __forceinline__ void cpasync16(uint32_t smem, const void* gptr) {
    asm volatile("cp.async.cg.shared.global [%0], [%1], 16;" :: "r"(smem), "l"(gptr));
}

// ---------------- big GEMM: raw = A_h[NE,128] @ B_h[128,4096] + col stats ----
// Persistent n-strip CTAs, 512 threads (16 warps, 4x4 warp grid, warp tile 32x32).
// A double-buffered via cp.async; B in SMEM (ldmatrix per ks); C staged via SMEM.
#define AS_STRIDE 136
#define TILE_B (128 * 136 * 2)          // 34816 B
#define SM_A0 0
#define SM_A1 TILE_B
#define SM_B  (TILE_B * 2)
#define SM_C  (TILE_B * 3)
#define GEMM_SMEM (TILE_B * 4 + 1024)
__global__ __launch_bounds__(512, 1) void k_gemm_edge() {
    extern __shared__ __align__(16) unsigned char sm[];
    __half* Cs = (__half*)(sm + SM_C);
    float* csum_s = (float*)(sm + TILE_B * 4);
    float* csq_s  = csum_s + 128;

    int tid = threadIdx.x;
    int warp = tid >> 5, lane = tid & 31;
    int wm = warp & 3, wn = warp >> 2;      // 4 (m, 32-rows) x 4 (n, 32-cols)
    int gid = lane >> 2, tig = lane & 3;
    int n0 = blockIdx.x * 128;
    int mb0 = blockIdx.y;

    uint32_t sb = (uint32_t)__cvta_generic_to_shared(sm);
    uint32_t a_sb[2] = { sb + SM_A0, sb + SM_A1 };
    uint32_t b_sb = sb + SM_B;

    // ---- prolog: B tile + A(mb0) ----
#pragma unroll
    for (int it = 0; it < 4; it++) {
        int idx = it * 512 + tid;
        int r = idx >> 4, c16 = idx & 15;
        cpasync16(b_sb + (r * AS_STRIDE + c16 * 8) * 2,
                  g_Bh + (size_t)r * DD + n0 + c16 * 8);
    }
#pragma unroll
    for (int it = 0; it < 4; it++) {
        int idx = it * 512 + tid;
        int r = idx >> 4, c16 = idx & 15;
        cpasync16(a_sb[0] + (r * AS_STRIDE + c16 * 8) * 2,
                  g_Ah + (size_t)(mb0 * 128 + r) * F + c16 * 8);
    }
    asm volatile("cp.async.commit_group;");
    if (tid < 128) { csum_s[tid] = 0.f; csq_s[tid] = 0.f; }
    asm volatile("cp.async.wait_group 0;");
    __syncthreads();

    float psum_r[8], psq_r[8];
#pragma unroll
    for (int j = 0; j < 8; j++) { psum_r[j] = 0.f; psq_r[j] = 0.f; }

    int buf = 0;
    for (int mb = mb0; mb < MBLK; mb += GY) {
        int mbn = mb + GY;
        if (mbn < MBLK) {
#pragma unroll
            for (int it = 0; it < 4; it++) {
                int idx = it * 512 + tid;
                int r = idx >> 4, c16 = idx & 15;
                cpasync16(a_sb[buf ^ 1] + (r * AS_STRIDE + c16 * 8) * 2,
                          g_Ah + (size_t)(mbn * 128 + r) * F + c16 * 8);
            }
            asm volatile("cp.async.commit_group;");
            asm volatile("cp.async.wait_group 1;");
        } else {
            asm volatile("cp.async.wait_group 0;");
        }
        __syncthreads();

        float c[2][4][4];
#pragma unroll
        for (int i = 0; i < 2; i++)
#pragma unroll
            for (int j = 0; j < 4; j++)
#pragma unroll
                for (int q = 0; q < 4; q++) c[i][j][q] = 0.f;

        uint32_t a_cur = a_sb[buf];
#pragma unroll
        for (int ks = 0; ks < 8; ks++) {
            uint32_t a[2][4], b[4][2];
#pragma unroll
            for (int mi = 0; mi < 2; mi++) {
                int row = wm * 32 + mi * 16 + (lane & 15);
                int kof = ks * 16 + ((lane >> 4) << 3);
                ldsm_x4(a[mi][0], a[mi][1], a[mi][2], a[mi][3],
                        a_cur + (row * AS_STRIDE + kof) * 2);
            }
#pragma unroll
            for (int hb = 0; hb < 2; hb++) {
                int krow = ks * 16 + (lane & 15);
                int ncol = wn * 32 + hb * 16 + ((lane >> 4) << 3);
                ldsm_x4_t(b[2 * hb][0], b[2 * hb][1], b[2 * hb + 1][0], b[2 * hb + 1][1],
                          b_sb + (krow * AS_STRIDE + ncol) * 2);
            }
#pragma unroll
            for (int mi = 0; mi < 2; mi++)
#pragma unroll
                for (int ni = 0; ni < 4; ni++)
                    mma16816(c[mi][ni], a[mi], b[ni]);
        }
        __syncthreads();   // all warps done reading A/B (and prior store done reading Cs)

        // stage C (fp16) + per-thread stats
#pragma unroll
        for (int mi = 0; mi < 2; mi++) {
#pragma unroll
            for (int ni = 0; ni < 4; ni++) {
                int row0 = wm * 32 + mi * 16 + gid;
                int col = wn * 32 + ni * 8 + tig * 2;
                *reinterpret_cast<__half2*>(&Cs[row0 * AS_STRIDE + col]) =
                    __floats2half2_rn(c[mi][ni][0], c[mi][ni][1]);
                *reinterpret_cast<__half2*>(&Cs[(row0 + 8) * AS_STRIDE + col]) =
                    __floats2half2_rn(c[mi][ni][2], c[mi][ni][3]);
                psum_r[ni * 2]     += c[mi][ni][0] + c[mi][ni][2];
                psum_r[ni * 2 + 1] += c[mi][ni][1] + c[mi][ni][3];
                psq_r[ni * 2]      += c[mi][ni][0] * c[mi][ni][0] + c[mi][ni][2] * c[mi][ni][2];
                psq_r[ni * 2 + 1]  += c[mi][ni][1] * c[mi][ni][1] + c[mi][ni][3] * c[mi][ni][3];
            }
        }
        __syncthreads();

        // coalesced fp16 store: 4 threads per row, 32 halves (64B) each
        {
            int r = tid >> 2, seg = tid & 3;
            int m = mb * 128 + r;
            if (m < NE) {
                __half* dst = raw_row(m) + n0 + seg * 32;
                const __half* src = &Cs[r * AS_STRIDE + seg * 32];
#pragma unroll
                for (int q = 0; q < 4; q++)
                    *reinterpret_cast<uint4*>(&dst[q * 8]) =
                        *reinterpret_cast<const uint4*>(&src[q * 8]);
            }
        }
        __syncthreads();
        buf ^= 1;
    }

    // ---- per-CTA stats reduction -> global ----
#pragma unroll
    for (int ni = 0; ni < 4; ni++) {
#pragma unroll
        for (int t = 0; t < 2; t++) {
            int col = wn * 32 + ni * 8 + tig * 2 + t;
            atomicAdd(&csum_s[col], psum_r[ni * 2 + t]);
            atomicAdd(&csq_s[col],  psq_r[ni * 2 + t]);
        }
    }
    __syncthreads();
    if (tid < 128) {
        atomicAdd(&g_colsum[n0 + tid], csum_s[tid]);
        atomicAdd(&g_colsq[n0 + tid],  csq_s[tid]);
    }
}

// ---------------- BN coefficients ----------------
__global__ void k_bncoef(const float* __restrict__ gamma, const float* __restrict__ beta) {
    int i = blockIdx.x * 256 + threadIdx.x;
    if (i < DD) {
        float mu  = g_colsum[i] * (1.0f / NE);
        float var = g_colsq[i] * (1.0f / NE) - mu * mu;
        float a = gamma[i] * rsqrtf(var + EPSV);
        g_a[i] = a;
        g_c[i] = beta[i] - mu * a;
    }
}

// ---------------- message + scatter: agg[dst] += x[src] . (a*raw + c) -------------
__global__ __launch_bounds__(256) void k_msg(const float* __restrict__ x0,
                                             const int* __restrict__ ei,
                                             int first) {
    __shared__ __align__(16) float a_s[DD];
    __shared__ __align__(16) float c_s[DD];
    __shared__ float xs[8][D];

    const float* __restrict__ x = first ? x0 : (const float*)g_node;
    int tid = threadIdx.x;
    for (int i = tid * 4; i < DD; i += 1024) {
        *reinterpret_cast<float4*>(&a_s[i]) = *reinterpret_cast<const float4*>(&g_a[i]);
        *reinterpret_cast<float4*>(&c_s[i]) = *reinterpret_cast<const float4*>(&g_c[i]);
    }
    __syncthreads();

    int warp = tid >> 5, lane = tid & 31;
    int gw = blockIdx.x * 8 + warp;
    int k = lane * 2;

    for (int e = gw; e < NE; e += gridDim.x * 8) {
        int src = ei[e];
        int dst = ei[NE + e];
        xs[warp][lane]      = x[src * D + lane];
        xs[warp][lane + 32] = x[src * D + lane + 32];
        __syncwarp();

        const __half* rp = raw_row(e);
        float acc0 = 0.f, acc1 = 0.f;
#pragma unroll
        for (int d = 0; d < D; d++) {
            __half2 h = *reinterpret_cast<const __half2*>(rp + d * D + k);
            float2 r = __half22float2(h);
            float xv = xs[warp][d];
            int i0 = d * D + k;
            acc0 = fmaf(xv, fmaf(a_s[i0],     r.x, c_s[i0]),     acc0);
            acc1 = fmaf(xv, fmaf(a_s[i0 + 1], r.y, c_s[i0 + 1]), acc1);
        }
        atomicAdd(&g_agg[dst * D + k],     acc0);
        atomicAdd(&g_agg[dst * D + k + 1], acc1);
        __syncwarp();
    }
}

// ---------------- fused GRU: xin inline + GEMVs in SMEM + gates + acc/out ---------
#define GRU_SMEM (2048 * 4 * 2 + 32 * 192 * 4 * 2)   // 65536 B
__global__ __launch_bounds__(192) void k_gru(const float* __restrict__ x0,
                                             const float* __restrict__ Wih,
                                             const float* __restrict__ Whh,
                                             const float* __restrict__ b_ih,
                                             const float* __restrict__ b_hh,
                                             const float* __restrict__ bias,
                                             float* __restrict__ out,
                                             int first, int last) {
    extern __shared__ __align__(16) unsigned char smg[];
    float* xs   = (float*)smg;
    float* hs   = xs + 2048;
    float* gi_s = hs + 2048;
    float* gh_s = gi_s + 32 * 192;

    const float* __restrict__ h = first ? x0 : (const float*)g_node;
    int tid = threadIdx.x;
    int base = blockIdx.x * 32;

    // stage: xin = relu(agg*inv + bias) computed inline; agg re-zeroed
    for (int f4 = tid; f4 < 512; f4 += 192) {
        int nb = base + (f4 >> 4);
        int c4 = (f4 & 15) * 4;
        float4 v = make_float4(0.f, 0.f, 0.f, 0.f), w = v;
        if (nb < NN) {
            float4 ag = *reinterpret_cast<const float4*>(&g_agg[nb * D + c4]);
            float iv = g_inv[nb];
            v.x = fmaxf(fmaf(ag.x, iv, bias[c4 + 0]), 0.f);
            v.y = fmaxf(fmaf(ag.y, iv, bias[c4 + 1]), 0.f);
            v.z = fmaxf(fmaf(ag.z, iv, bias[c4 + 2]), 0.f);
            v.w = fmaxf(fmaf(ag.w, iv, bias[c4 + 3]), 0.f);
            *reinterpret_cast<float4*>(&g_agg[nb * D + c4]) = make_float4(0.f, 0.f, 0.f, 0.f);
            w = *reinterpret_cast<const float4*>(&h[nb * D + c4]);
        }
        *reinterpret_cast<float4*>(&xs[f4 * 4]) = v;
        *reinterpret_cast<float4*>(&hs[f4 * 4]) = w;
    }
    __syncthreads();

    {
        float4 wr[16];
#pragma unroll
        for (int q = 0; q < 16; q++) wr[q] = reinterpret_cast<const float4*>(Wih)[tid * 16 + q];
        for (int nn = 0; nn < 32; nn++) {
            float acc = 0.f;
#pragma unroll
            for (int q = 0; q < 16; q++) {
                float4 xv = *reinterpret_cast<float4*>(&xs[nn * D + q * 4]);
                float4 wv = wr[q];
                acc = fmaf(xv.x, wv.x, acc); acc = fmaf(xv.y, wv.y, acc);
                acc = fmaf(xv.z, wv.z, acc); acc = fmaf(xv.w, wv.w, acc);
            }
            gi_s[nn * 192 + tid] = acc;
        }
#pragma unroll
        for (int q = 0; q < 16; q++) wr[q] = reinterpret_cast<const float4*>(Whh)[tid * 16 + q];
        for (int nn = 0; nn < 32; nn++) {
            float acc = 0.f;
#pragma unroll
            for (int q = 0; q < 16; q++) {
                float4 xv = *reinterpret_cast<float4*>(&hs[nn * D + q * 4]);
                float4 wv = wr[q];
                acc = fmaf(xv.x, wv.x, acc); acc = fmaf(xv.y, wv.y, acc);
                acc = fmaf(xv.z, wv.z, acc); acc = fmaf(xv.w, wv.w, acc);
            }
            gh_s[nn * 192 + tid] = acc;
        }
    }
    __syncthreads();

    for (int i = tid; i < 2048; i += 192) {
        int gidx = base * D + i;
        if (gidx >= NN * D) break;
        int nl = i >> 6, j = i & 63;

        float ir = gi_s[nl * 192 + j]       + b_ih[j];
        float iz = gi_s[nl * 192 + 64 + j]  + b_ih[64 + j];
        float in = gi_s[nl * 192 + 128 + j] + b_ih[128 + j];
        float hr = gh_s[nl * 192 + j]       + b_hh[j];
        float hz = gh_s[nl * 192 + 64 + j]  + b_hh[64 + j];
        float hn = gh_s[nl * 192 + 128 + j] + b_hh[128 + j];

        float r = 1.0f / (1.0f + expf(-(ir + hr)));
        float z = 1.0f / (1.0f + expf(-(iz + hz)));
        float nv = tanhf(fmaf(r, hn, in));

        float hold = hs[i];
        float hnew = fmaf(z, hold - nv, nv);   // (1-z)*n + z*h

        if (last) {
            out[gidx] = (g_acc[gidx] + hold + hnew) * 0.25f + x0[gidx];
        } else {
            if (first) g_acc[gidx] = hold;
            else       g_acc[gidx] += hold;
            g_node[gidx] = hnew;
        }
    }
}

// ---------------- launcher ----------------
extern "C" void kernel_launch(void* const* d_in, const int* in_sizes, int n_in,
                              void* d_out, int out_size) {
    const float* node   = (const float*)d_in[0];
    const int*   ei     = (const int*)d_in[1];     // int32 (JAX x64 disabled)
    const float* edge   = (const float*)d_in[2];
    const float* W_edge = (const float*)d_in[3];
    const float* gamma  = (const float*)d_in[4];
    const float* beta   = (const float*)d_in[5];
    const float* bias   = (const float*)d_in[6];
    const float* W_ih   = (const float*)d_in[7];
    const float* W_hh   = (const float*)d_in[8];
    const float* b_ih   = (const float*)d_in[9];
    const float* b_hh   = (const float*)d_in[10];
    float* out = (float*)d_out;

    cudaFuncSetAttribute(k_gemm_edge, cudaFuncAttributeMaxDynamicSharedMemorySize, GEMM_SMEM);
    cudaFuncSetAttribute(k_gru, cudaFuncAttributeMaxDynamicSharedMemorySize, GRU_SMEM);

    int nelem_blocks = (NN * D + 255) / 256;
    k_zero_pre<<<nelem_blocks, 256>>>();
    k_count<<<(NE + 255) / 256, 256>>>(ei);
    k_inv<<<196, 256>>>();

    k_toh_A<<<(NEPAD * F / 8 + 255) / 256, 256>>>(edge);
    k_toh_B<<<(F * DD / 8 + 255) / 256, 256>>>(W_edge);

    dim3 gg(DD / 128, GY);
    k_gemm_edge<<<gg, 512, GEMM_SMEM>>>();
    k_bncoef<<<16, 256>>>(gamma, beta);

    // only 3 propagation steps needed: out = x0 + mean(node_0..node_3);
    // the reference's 4th GRU update is dead code.
    for (int s = 0; s < 3; s++) {
        int first = (s == 0) ? 1 : 0;
        int last = (s == 2) ? 1 : 0;
        k_msg<<<1184, 256>>>(node, ei, first);
        k_gru<<<(NN + 31) / 32, 192, GRU_SMEM>>>(node, W_ih, W_hh, b_ih, b_hh, bias, out, first, last);
    }
}

// round 13
// speedup vs baseline: 1.0664x; 1.0664x over previous
#include <cuda_runtime.h>
#include <cuda_fp16.h>
#include <math.h>
#include <stdint.h>

#define NN 50000
#define NE 100000
#define D  64
#define F  128
#define DD 4096
#define EPSV 1e-5f
#define ECHUNK 25600
#define NEPAD 100096
#define MBLK 782       // NEPAD / 128
#define GY 37          // 32*37 = 1184 CTAs = 8 waves of 148

// ---------------- scratch (static device globals; no runtime alloc) ----------------
__device__ __align__(16) __half g_raw0[(size_t)ECHUNK * DD];
__device__ __align__(16) __half g_raw1[(size_t)ECHUNK * DD];
__device__ __align__(16) __half g_raw2[(size_t)ECHUNK * DD];
__device__ __align__(16) __half g_raw3[(size_t)ECHUNK * DD];

__device__ __forceinline__ __half* raw_row(int e) {
    int c = e / ECHUNK;
    int r = e - c * ECHUNK;
    __half* base = (c == 0) ? g_raw0 : (c == 1) ? g_raw1 : (c == 2) ? g_raw2 : g_raw3;
    return base + (size_t)r * DD;
}

__device__ __align__(16) __half g_Ah[(size_t)NEPAD * F];   // 25.6 MB
__device__ __align__(16) __half g_Bh[(size_t)F * DD];      // 1 MB  [k][n]

__device__ __align__(16) float g_colsum[DD];
__device__ __align__(16) float g_colsq[DD];
__device__ __align__(16) float g_a[DD];
__device__ __align__(16) float g_c[DD];
__device__ __align__(16) float g_cnt[NN];
__device__ __align__(16) float g_inv[NN];
__device__ __align__(16) float g_agg[NN * D];
__device__ __align__(16) float g_node[NN * D];
__device__ __align__(16) float g_acc[NN * D];

struct alignas(8) H4 { __half2 x, y; };

// ---------------- zero / count helpers ----------------
__global__ void k_zero_pre() {
    int i = blockIdx.x * 256 + threadIdx.x;
    if (i < DD) { g_colsum[i] = 0.f; g_colsq[i] = 0.f; }
    if (i < NN) g_cnt[i] = 0.f;
    if (i < NN * D) g_agg[i] = 0.f;
}

__global__ void k_count(const int* __restrict__ ei) {
    int e = blockIdx.x * 256 + threadIdx.x;
    if (e < NE) atomicAdd(&g_cnt[ei[NE + e]], 1.0f);
}

__global__ void k_inv() {
    int i = blockIdx.x * 256 + threadIdx.x;
    if (i < NN) g_inv[i] = 1.0f / fmaxf(g_cnt[i], 1.0f);
}

// ---------------- fp32 -> fp16 pre-conversion ----------------
__global__ void k_toh_A(const float* __restrict__ A) {
    int i = blockIdx.x * 256 + threadIdx.x;   // one per 8 elems
    if (i >= NEPAD * F / 8) return;
    int r = i / (F / 8);
    H4 h0, h1;
    if (r < NE) {
        const float4* s = reinterpret_cast<const float4*>(A) + (size_t)i * 2;
        float4 v0 = s[0], v1 = s[1];
        h0.x = __floats2half2_rn(v0.x, v0.y); h0.y = __floats2half2_rn(v0.z, v0.w);
        h1.x = __floats2half2_rn(v1.x, v1.y); h1.y = __floats2half2_rn(v1.z, v1.w);
    } else {
        h0.x = h0.y = h1.x = h1.y = __floats2half2_rn(0.f, 0.f);
    }
    H4* d = reinterpret_cast<H4*>(g_Ah) + (size_t)i * 2;
    d[0] = h0; d[1] = h1;
}

__global__ void k_toh_B(const float* __restrict__ B) {
    int i = blockIdx.x * 256 + threadIdx.x;
    if (i >= F * DD / 8) return;
    const float4* s = reinterpret_cast<const float4*>(B) + (size_t)i * 2;
    float4 v0 = s[0], v1 = s[1];
    H4 h0, h1;
    h0.x = __floats2half2_rn(v0.x, v0.y); h0.y = __floats2half2_rn(v0.z, v0.w);
    h1.x = __floats2half2_rn(v1.x, v1.y); h1.y = __floats2half2_rn(v1.z, v1.w);
    H4* d = reinterpret_cast<H4*>(g_Bh) + (size_t)i * 2;
    d[0] = h0; d[1] = h1;
}

// ---------------- tensor-core GEMM helpers ----------------
__device__ __forceinline__ void ldsm_x4(uint32_t& r0, uint32_t& r1, uint32_t& r2, uint32_t& r3,
                                        uint32_t addr) {
    asm volatile("ldmatrix.sync.aligned.m8n8.x4.shared.b16 {%0,%1,%2,%3}, [%4];"
                 : "=r"(r0), "=r"(r1), "=r"(r2), "=r"(r3) : "r"(addr));
}
__device__ __forceinline__ void ldsm_x4_t(uint32_t& r0, uint32_t& r1, uint32_t& r2, uint32_t& r3,
                                          uint32_t addr) {
    asm volatile("ldmatrix.sync.aligned.m8n8.x4.trans.shared.b16 {%0,%1,%2,%3}, [%4];"
                 : "=r"(r0), "=r"(r1), "=r"(r2), "=r"(r3) : "r"(addr));
}
__device__ __forceinline__ void mma16816(float* c, const uint32_t* a, const uint32_t* b) {
    asm volatile(
        "mma.sync.aligned.m16n8k16.row.col.f32.f16.f16.f32 "
        "{%0,%1,%2,%3}, {%4,%5,%6,%7}, {%8,%9}, {%0,%1,%2,%3};"
        : "+f"(c[0]), "+f"(c[1]), "+f"(c[2]), "+f"(c[3])
        : "r"(a[0]), "r"(a[1]), "r"(a[2]), "r"(a[3]), "r"(b[0]), "r"(b[1]));
}
__device__ __forceinline__ void cpasync16(uint32_t smem, const void* gptr) {
    asm volatile("cp.async.cg.shared.global [%0], [%1], 16;" :: "r"(smem), "l"(gptr));
}

// ---------------- big GEMM: raw = A_h[NE,128] @ B_h[128,4096] + col stats ----
// Persistent n-strip CTAs; 8 warps (2m x 4n), warp tile 64x32; B in REGISTERS
// (loop-invariant); A double-buffered cp.async; PER-WARP epilogue (disjoint C
// regions, __syncwarp only). 2 block syncs per tile.
#define AS_STRIDE 136
#define CS_STRIDE 136
#define TILE_B (128 * 136 * 2)          // 34816 B
#define SM_A0 0
#define SM_A1 TILE_B
#define SM_BC (TILE_B * 2)
#define GEMM_SMEM (TILE_B * 3 + 1024)
__global__ __launch_bounds__(256) void k_gemm_edge() {
    extern __shared__ __align__(16) unsigned char sm[];
    __half* Cs = (__half*)(sm + SM_BC);              // B tile at prolog, then C staging
    float* csum_s = (float*)(sm + TILE_B * 3);
    float* csq_s  = csum_s + 128;

    int tid = threadIdx.x;
    int warp = tid >> 5, lane = tid & 31;
    int wm = warp & 1, wn = warp >> 1;      // 2 (m, 64 rows) x 4 (n, 32 cols)
    int gid = lane >> 2, tig = lane & 3;
    int n0 = blockIdx.x * 128;
    int mb0 = blockIdx.y;

    uint32_t sb = (uint32_t)__cvta_generic_to_shared(sm);
    uint32_t a_sb[2] = { sb + SM_A0, sb + SM_A1 };
    uint32_t bc_sb = sb + SM_BC;

    // ---- prolog: B tile (into BC) + A(mb0) in one group ----
#pragma unroll
    for (int it = 0; it < 8; it++) {
        int idx = it * 256 + tid;
        int r = idx >> 4, c16 = idx & 15;
        cpasync16(bc_sb + (r * AS_STRIDE + c16 * 8) * 2,
                  g_Bh + (size_t)r * DD + n0 + c16 * 8);
    }
#pragma unroll
    for (int it = 0; it < 8; it++) {
        int idx = it * 256 + tid;
        int r = idx >> 4, c16 = idx & 15;
        cpasync16(a_sb[0] + (r * AS_STRIDE + c16 * 8) * 2,
                  g_Ah + (size_t)(mb0 * 128 + r) * F + c16 * 8);
    }
    asm volatile("cp.async.commit_group;");
    if (tid < 128) { csum_s[tid] = 0.f; csq_s[tid] = 0.f; }
    asm volatile("cp.async.wait_group 0;");
    __syncthreads();

    // ---- B fragments -> registers (loop-invariant) ----
    uint32_t bfr[8][4][2];
#pragma unroll
    for (int ks = 0; ks < 8; ks++) {
#pragma unroll
        for (int hb = 0; hb < 2; hb++) {
            int krow = ks * 16 + (lane & 15);
            int ncol = wn * 32 + hb * 16 + ((lane >> 4) << 3);
            ldsm_x4_t(bfr[ks][2 * hb][0], bfr[ks][2 * hb][1],
                      bfr[ks][2 * hb + 1][0], bfr[ks][2 * hb + 1][1],
                      bc_sb + (krow * AS_STRIDE + ncol) * 2);
        }
    }

    float csum_r[8], csq_r[8];
#pragma unroll
    for (int j = 0; j < 8; j++) { csum_r[j] = 0.f; csq_r[j] = 0.f; }

    int buf = 0;
    for (int mb = mb0; mb < MBLK; mb += GY) {
        int mbn = mb + GY;
        // sync 1: all warps done reading A[buf^1] (prev mainloop) and BC (prolog B reads)
        __syncthreads();
        if (mbn < MBLK) {
#pragma unroll
            for (int it = 0; it < 8; it++) {
                int idx = it * 256 + tid;
                int r = idx >> 4, c16 = idx & 15;
                cpasync16(a_sb[buf ^ 1] + (r * AS_STRIDE + c16 * 8) * 2,
                          g_Ah + (size_t)(mbn * 128 + r) * F + c16 * 8);
            }
            asm volatile("cp.async.commit_group;");
            asm volatile("cp.async.wait_group 1;");
        } else {
            asm volatile("cp.async.wait_group 0;");
        }
        // sync 2: A[buf] visible to all threads
        __syncthreads();

        float c[4][4][4];
#pragma unroll
        for (int i = 0; i < 4; i++)
#pragma unroll
            for (int j = 0; j < 4; j++)
#pragma unroll
                for (int q = 0; q < 4; q++) c[i][j][q] = 0.f;

        uint32_t a_cur = a_sb[buf];
#pragma unroll
        for (int ks = 0; ks < 8; ks++) {
            uint32_t a[4][4];
#pragma unroll
            for (int mi = 0; mi < 4; mi++) {
                int row = wm * 64 + mi * 16 + (lane & 15);
                int kof = ks * 16 + ((lane >> 4) << 3);
                ldsm_x4(a[mi][0], a[mi][1], a[mi][2], a[mi][3],
                        a_cur + (row * AS_STRIDE + kof) * 2);
            }
#pragma unroll
            for (int mi = 0; mi < 4; mi++)
#pragma unroll
                for (int ni = 0; ni < 4; ni++)
                    mma16816(c[mi][ni], a[mi], bfr[ks][ni]);
        }

        // ---- PER-WARP epilogue: stage own 64x32 region, store, stats ----
#pragma unroll
        for (int mi = 0; mi < 4; mi++) {
#pragma unroll
            for (int ni = 0; ni < 4; ni++) {
                int row0 = wm * 64 + mi * 16 + gid;
                int col = wn * 32 + ni * 8 + tig * 2;
                *reinterpret_cast<__half2*>(&Cs[row0 * CS_STRIDE + col]) =
                    __floats2half2_rn(c[mi][ni][0], c[mi][ni][1]);
                *reinterpret_cast<__half2*>(&Cs[(row0 + 8) * CS_STRIDE + col]) =
                    __floats2half2_rn(c[mi][ni][2], c[mi][ni][3]);
                csum_r[ni * 2]     += c[mi][ni][0] + c[mi][ni][2];
                csum_r[ni * 2 + 1] += c[mi][ni][1] + c[mi][ni][3];
                csq_r[ni * 2]      += c[mi][ni][0] * c[mi][ni][0] + c[mi][ni][2] * c[mi][ni][2];
                csq_r[ni * 2 + 1]  += c[mi][ni][1] * c[mi][ni][1] + c[mi][ni][3] * c[mi][ni][3];
            }
        }
        __syncwarp();
        // store own region: 8 passes, 4 lanes per row (16B each = 64B/row)
#pragma unroll
        for (int p = 0; p < 8; p++) {
            int rl = wm * 64 + p * 8 + (lane >> 2);
            int seg = lane & 3;
            int m = mb * 128 + rl;
            if (m < NE) {
                *reinterpret_cast<uint4*>(raw_row(m) + n0 + wn * 32 + seg * 8) =
                    *reinterpret_cast<const uint4*>(&Cs[rl * CS_STRIDE + wn * 32 + seg * 8]);
            }
        }
        __syncwarp();
        buf ^= 1;
    }

    // ---- per-CTA stats reduction -> global ----
    __syncthreads();
#pragma unroll
    for (int ni = 0; ni < 4; ni++) {
#pragma unroll
        for (int t = 0; t < 2; t++) {
            int col = wn * 32 + ni * 8 + tig * 2 + t;
            atomicAdd(&csum_s[col], csum_r[ni * 2 + t]);
            atomicAdd(&csq_s[col],  csq_r[ni * 2 + t]);
        }
    }
    __syncthreads();
    if (tid < 128) {
        atomicAdd(&g_colsum[n0 + tid], csum_s[tid]);
        atomicAdd(&g_colsq[n0 + tid],  csq_s[tid]);
    }
}

// ---------------- BN coefficients ----------------
__global__ void k_bncoef(const float* __restrict__ gamma, const float* __restrict__ beta) {
    int i = blockIdx.x * 256 + threadIdx.x;
    if (i < DD) {
        float mu  = g_colsum[i] * (1.0f / NE);
        float var = g_colsq[i] * (1.0f / NE) - mu * mu;
        float a = gamma[i] * rsqrtf(var + EPSV);
        g_a[i] = a;
        g_c[i] = beta[i] - mu * a;
    }
}

// ---------------- message + scatter: agg[dst] += x[src] . (a*raw + c) -------------
__global__ __launch_bounds__(256) void k_msg(const float* __restrict__ x0,
                                             const int* __restrict__ ei,
                                             int first) {
    __shared__ __align__(16) float a_s[DD];
    __shared__ __align__(16) float c_s[DD];
    __shared__ float xs[8][D];

    const float* __restrict__ x = first ? x0 : (const float*)g_node;
    int tid = threadIdx.x;
    for (int i = tid * 4; i < DD; i += 1024) {
        *reinterpret_cast<float4*>(&a_s[i]) = *reinterpret_cast<const float4*>(&g_a[i]);
        *reinterpret_cast<float4*>(&c_s[i]) = *reinterpret_cast<const float4*>(&g_c[i]);
    }
    __syncthreads();

    int warp = tid >> 5, lane = tid & 31;
    int gw = blockIdx.x * 8 + warp;
    int k = lane * 2;

    for (int e = gw; e < NE; e += gridDim.x * 8) {
        int src = ei[e];
        int dst = ei[NE + e];
        xs[warp][lane]      = x[src * D + lane];
        xs[warp][lane + 32] = x[src * D + lane + 32];
        __syncwarp();

        const __half* rp = raw_row(e);
        float acc0 = 0.f, acc1 = 0.f;
#pragma unroll
        for (int d = 0; d < D; d++) {
            __half2 h = *reinterpret_cast<const __half2*>(rp + d * D + k);
            float2 r = __half22float2(h);
            float xv = xs[warp][d];
            int i0 = d * D + k;
            acc0 = fmaf(xv, fmaf(a_s[i0],     r.x, c_s[i0]),     acc0);
            acc1 = fmaf(xv, fmaf(a_s[i0 + 1], r.y, c_s[i0 + 1]), acc1);
        }
        atomicAdd(&g_agg[dst * D + k],     acc0);
        atomicAdd(&g_agg[dst * D + k + 1], acc1);
        __syncwarp();
    }
}

// ---------------- fused GRU: xin inline + GEMVs in SMEM + gates + acc/out ---------
#define GRU_SMEM (2048 * 4 * 2 + 32 * 192 * 4 * 2)   // 65536 B
__global__ __launch_bounds__(192) void k_gru(const float* __restrict__ x0,
                                             const float* __restrict__ Wih,
                                             const float* __restrict__ Whh,
                                             const float* __restrict__ b_ih,
                                             const float* __restrict__ b_hh,
                                             const float* __restrict__ bias,
                                             float* __restrict__ out,
                                             int first, int last) {
    extern __shared__ __align__(16) unsigned char smg[];
    float* xs   = (float*)smg;
    float* hs   = xs + 2048;
    float* gi_s = hs + 2048;
    float* gh_s = gi_s + 32 * 192;

    const float* __restrict__ h = first ? x0 : (const float*)g_node;
    int tid = threadIdx.x;
    int base = blockIdx.x * 32;

    // stage: xin = relu(agg*inv + bias) computed inline; agg re-zeroed
    for (int f4 = tid; f4 < 512; f4 += 192) {
        int nb = base + (f4 >> 4);
        int c4 = (f4 & 15) * 4;
        float4 v = make_float4(0.f, 0.f, 0.f, 0.f), w = v;
        if (nb < NN) {
            float4 ag = *reinterpret_cast<const float4*>(&g_agg[nb * D + c4]);
            float iv = g_inv[nb];
            v.x = fmaxf(fmaf(ag.x, iv, bias[c4 + 0]), 0.f);
            v.y = fmaxf(fmaf(ag.y, iv, bias[c4 + 1]), 0.f);
            v.z = fmaxf(fmaf(ag.z, iv, bias[c4 + 2]), 0.f);
            v.w = fmaxf(fmaf(ag.w, iv, bias[c4 + 3]), 0.f);
            *reinterpret_cast<float4*>(&g_agg[nb * D + c4]) = make_float4(0.f, 0.f, 0.f, 0.f);
            w = *reinterpret_cast<const float4*>(&h[nb * D + c4]);
        }
        *reinterpret_cast<float4*>(&xs[f4 * 4]) = v;
        *reinterpret_cast<float4*>(&hs[f4 * 4]) = w;
    }
    __syncthreads();

    {
        float4 wr[16];
#pragma unroll
        for (int q = 0; q < 16; q++) wr[q] = reinterpret_cast<const float4*>(Wih)[tid * 16 + q];
        for (int nn = 0; nn < 32; nn++) {
            float acc = 0.f;
#pragma unroll
            for (int q = 0; q < 16; q++) {
                float4 xv = *reinterpret_cast<float4*>(&xs[nn * D + q * 4]);
                float4 wv = wr[q];
                acc = fmaf(xv.x, wv.x, acc); acc = fmaf(xv.y, wv.y, acc);
                acc = fmaf(xv.z, wv.z, acc); acc = fmaf(xv.w, wv.w, acc);
            }
            gi_s[nn * 192 + tid] = acc;
        }
#pragma unroll
        for (int q = 0; q < 16; q++) wr[q] = reinterpret_cast<const float4*>(Whh)[tid * 16 + q];
        for (int nn = 0; nn < 32; nn++) {
            float acc = 0.f;
#pragma unroll
            for (int q = 0; q < 16; q++) {
                float4 xv = *reinterpret_cast<float4*>(&hs[nn * D + q * 4]);
                float4 wv = wr[q];
                acc = fmaf(xv.x, wv.x, acc); acc = fmaf(xv.y, wv.y, acc);
                acc = fmaf(xv.z, wv.z, acc); acc = fmaf(xv.w, wv.w, acc);
            }
            gh_s[nn * 192 + tid] = acc;
        }
    }
    __syncthreads();

    for (int i = tid; i < 2048; i += 192) {
        int gidx = base * D + i;
        if (gidx >= NN * D) break;
        int nl = i >> 6, j = i & 63;

        float ir = gi_s[nl * 192 + j]       + b_ih[j];
        float iz = gi_s[nl * 192 + 64 + j]  + b_ih[64 + j];
        float in = gi_s[nl * 192 + 128 + j] + b_ih[128 + j];
        float hr = gh_s[nl * 192 + j]       + b_hh[j];
        float hz = gh_s[nl * 192 + 64 + j]  + b_hh[64 + j];
        float hn = gh_s[nl * 192 + 128 + j] + b_hh[128 + j];

        float r = 1.0f / (1.0f + expf(-(ir + hr)));
        float z = 1.0f / (1.0f + expf(-(iz + hz)));
        float nv = tanhf(fmaf(r, hn, in));

        float hold = hs[i];
        float hnew = fmaf(z, hold - nv, nv);   // (1-z)*n + z*h

        if (last) {
            out[gidx] = (g_acc[gidx] + hold + hnew) * 0.25f + x0[gidx];
        } else {
            if (first) g_acc[gidx] = hold;
            else       g_acc[gidx] += hold;
            g_node[gidx] = hnew;
        }
    }
}

// ---------------- launcher ----------------
extern "C" void kernel_launch(void* const* d_in, const int* in_sizes, int n_in,
                              void* d_out, int out_size) {
    const float* node   = (const float*)d_in[0];
    const int*   ei     = (const int*)d_in[1];     // int32 (JAX x64 disabled)
    const float* edge   = (const float*)d_in[2];
    const float* W_edge = (const float*)d_in[3];
    const float* gamma  = (const float*)d_in[4];
    const float* beta   = (const float*)d_in[5];
    const float* bias   = (const float*)d_in[6];
    const float* W_ih   = (const float*)d_in[7];
    const float* W_hh   = (const float*)d_in[8];
    const float* b_ih   = (const float*)d_in[9];
    const float* b_hh   = (const float*)d_in[10];
    float* out = (float*)d_out;

    cudaFuncSetAttribute(k_gemm_edge, cudaFuncAttributeMaxDynamicSharedMemorySize, GEMM_SMEM);
    cudaFuncSetAttribute(k_gru, cudaFuncAttributeMaxDynamicSharedMemorySize, GRU_SMEM);

    int nelem_blocks = (NN * D + 255) / 256;
    k_zero_pre<<<nelem_blocks, 256>>>();
    k_count<<<(NE + 255) / 256, 256>>>(ei);
    k_inv<<<196, 256>>>();

    k_toh_A<<<(NEPAD * F / 8 + 255) / 256, 256>>>(edge);
    k_toh_B<<<(F * DD / 8 + 255) / 256, 256>>>(W_edge);

    dim3 gg(DD / 128, GY);
    k_gemm_edge<<<gg, 256, GEMM_SMEM>>>();
    k_bncoef<<<16, 256>>>(gamma, beta);

    // only 3 propagation steps needed: out = x0 + mean(node_0..node_3);
    // the reference's 4th GRU update is dead code.
    for (int s = 0; s < 3; s++) {
        int first = (s == 0) ? 1 : 0;
        int last = (s == 2) ? 1 : 0;
        k_msg<<<1184, 256>>>(node, ei, first);
        k_gru<<<(NN + 31) / 32, 192, GRU_SMEM>>>(node, W_ih, W_hh, b_ih, b_hh, bias, out, first, last);
    }
}

// round 14
// speedup vs baseline: 1.1224x; 1.0524x over previous
#include <cuda_runtime.h>
#include <cuda_fp16.h>
#include <math.h>
#include <stdint.h>

#define NN 50000
#define NE 100000
#define D  64
#define F  128
#define DD 4096
#define EPSV 1e-5f
#define ECHUNK 25600
#define NEPAD 100096
#define MBLK 782       // NEPAD / 128
#define GY 74          // 32*74 = 2368 CTAs = 8 waves of 296 (2 CTAs/SM)

// ---------------- scratch (static device globals; no runtime alloc) ----------------
__device__ __align__(16) __half g_raw0[(size_t)ECHUNK * DD];
__device__ __align__(16) __half g_raw1[(size_t)ECHUNK * DD];
__device__ __align__(16) __half g_raw2[(size_t)ECHUNK * DD];
__device__ __align__(16) __half g_raw3[(size_t)ECHUNK * DD];

__device__ __forceinline__ __half* raw_row(int e) {
    int c = e / ECHUNK;
    int r = e - c * ECHUNK;
    __half* base = (c == 0) ? g_raw0 : (c == 1) ? g_raw1 : (c == 2) ? g_raw2 : g_raw3;
    return base + (size_t)r * DD;
}

__device__ __align__(16) __half g_Ah[(size_t)NEPAD * F];   // 25.6 MB
__device__ __align__(16) __half g_Bh[(size_t)F * DD];      // 1 MB  [k][n]

__device__ __align__(16) float g_colsum[DD];
__device__ __align__(16) float g_colsq[DD];
__device__ __align__(16) float g_a[DD];
__device__ __align__(16) float g_c[DD];
__device__ __align__(16) float g_cnt[NN];
__device__ __align__(16) float g_inv[NN];
__device__ __align__(16) float g_agg[NN * D];
__device__ __align__(16) float g_node[NN * D];
__device__ __align__(16) float g_acc[NN * D];

struct alignas(8) H4 { __half2 x, y; };

// ---------------- zero / count helpers ----------------
__global__ void k_zero_pre() {
    int i = blockIdx.x * 256 + threadIdx.x;
    if (i < DD) { g_colsum[i] = 0.f; g_colsq[i] = 0.f; }
    if (i < NN) g_cnt[i] = 0.f;
    if (i < NN * D) g_agg[i] = 0.f;
}

__global__ void k_count(const int* __restrict__ ei) {
    int e = blockIdx.x * 256 + threadIdx.x;
    if (e < NE) atomicAdd(&g_cnt[ei[NE + e]], 1.0f);
}

__global__ void k_inv() {
    int i = blockIdx.x * 256 + threadIdx.x;
    if (i < NN) g_inv[i] = 1.0f / fmaxf(g_cnt[i], 1.0f);
}

// ---------------- fp32 -> fp16 pre-conversion ----------------
__global__ void k_toh_A(const float* __restrict__ A) {
    int i = blockIdx.x * 256 + threadIdx.x;   // one per 8 elems
    if (i >= NEPAD * F / 8) return;
    int r = i / (F / 8);
    H4 h0, h1;
    if (r < NE) {
        const float4* s = reinterpret_cast<const float4*>(A) + (size_t)i * 2;
        float4 v0 = s[0], v1 = s[1];
        h0.x = __floats2half2_rn(v0.x, v0.y); h0.y = __floats2half2_rn(v0.z, v0.w);
        h1.x = __floats2half2_rn(v1.x, v1.y); h1.y = __floats2half2_rn(v1.z, v1.w);
    } else {
        h0.x = h0.y = h1.x = h1.y = __floats2half2_rn(0.f, 0.f);
    }
    H4* d = reinterpret_cast<H4*>(g_Ah) + (size_t)i * 2;
    d[0] = h0; d[1] = h1;
}

__global__ void k_toh_B(const float* __restrict__ B) {
    int i = blockIdx.x * 256 + threadIdx.x;
    if (i >= F * DD / 8) return;
    const float4* s = reinterpret_cast<const float4*>(B) + (size_t)i * 2;
    float4 v0 = s[0], v1 = s[1];
    H4 h0, h1;
    h0.x = __floats2half2_rn(v0.x, v0.y); h0.y = __floats2half2_rn(v0.z, v0.w);
    h1.x = __floats2half2_rn(v1.x, v1.y); h1.y = __floats2half2_rn(v1.z, v1.w);
    H4* d = reinterpret_cast<H4*>(g_Bh) + (size_t)i * 2;
    d[0] = h0; d[1] = h1;
}

// ---------------- tensor-core GEMM helpers ----------------
__device__ __forceinline__ void ldsm_x4(uint32_t& r0, uint32_t& r1, uint32_t& r2, uint32_t& r3,
                                        uint32_t addr) {
    asm volatile("ldmatrix.sync.aligned.m8n8.x4.shared.b16 {%0,%1,%2,%3}, [%4];"
                 : "=r"(r0), "=r"(r1), "=r"(r2), "=r"(r3) : "r"(addr));
}
__device__ __forceinline__ void ldsm_x4_t(uint32_t& r0, uint32_t& r1, uint32_t& r2, uint32_t& r3,
                                          uint32_t addr) {
    asm volatile("ldmatrix.sync.aligned.m8n8.x4.trans.shared.b16 {%0,%1,%2,%3}, [%4];"
                 : "=r"(r0), "=r"(r1), "=r"(r2), "=r"(r3) : "r"(addr));
}
__device__ __forceinline__ void mma16816(float* c, const uint32_t* a, const uint32_t* b) {
    asm volatile(
        "mma.sync.aligned.m16n8k16.row.col.f32.f16.f16.f32 "
        "{%0,%1,%2,%3}, {%4,%5,%6,%7}, {%8,%9}, {%0,%1,%2,%3};"
        : "+f"(c[0]), "+f"(c[1]), "+f"(c[2]), "+f"(c[3])
        : "r"(a[0]), "r"(a[1]), "r"(a[2]), "r"(a[3]), "r"(b[0]), "r"(b[1]));
}
__device__ __forceinline__ void cpasync16(uint32_t smem, const void* gptr) {
    asm volatile("cp.async.cg.shared.global [%0], [%1], 16;" :: "r"(smem), "l"(gptr));
}

// ---------------- big GEMM: raw = A_h[NE,128] @ B_h[128,4096] + col stats ----
// Persistent n-strip CTAs at 2 CTAs/SM. 8 warps (2m x 4n), warp tile 64x32.
// B resident in SMEM (ldsm per ks); A double-buffered cp.async; C staged into
// the DEAD A buffer (extra sync covered by co-resident CTA). Regs <= 128.
#define AS_STRIDE 136
#define CS_STRIDE 136
#define TILE_B (128 * 136 * 2)          // 34816 B
#define SM_A0 0
#define SM_A1 TILE_B
#define SM_B  (TILE_B * 2)
#define GEMM_SMEM (TILE_B * 3 + 1024)   // 105472 B -> 2 CTAs/SM
__global__ __launch_bounds__(256, 2) void k_gemm_edge() {
    extern __shared__ __align__(16) unsigned char sm[];
    float* csum_s = (float*)(sm + TILE_B * 3);
    float* csq_s  = csum_s + 128;

    int tid = threadIdx.x;
    int warp = tid >> 5, lane = tid & 31;
    int wm = warp & 1, wn = warp >> 1;      // 2 (m, 64 rows) x 4 (n, 32 cols)
    int gid = lane >> 2, tig = lane & 3;
    int n0 = blockIdx.x * 128;
    int mb0 = blockIdx.y;

    uint32_t sb = (uint32_t)__cvta_generic_to_shared(sm);
    uint32_t a_sb[2] = { sb + SM_A0, sb + SM_A1 };
    uint32_t b_sb = sb + SM_B;

    // ---- prolog: B tile + A(mb0) in one group ----
#pragma unroll
    for (int it = 0; it < 8; it++) {
        int idx = it * 256 + tid;
        int r = idx >> 4, c16 = idx & 15;
        cpasync16(b_sb + (r * AS_STRIDE + c16 * 8) * 2,
                  g_Bh + (size_t)r * DD + n0 + c16 * 8);
    }
#pragma unroll
    for (int it = 0; it < 8; it++) {
        int idx = it * 256 + tid;
        int r = idx >> 4, c16 = idx & 15;
        cpasync16(a_sb[0] + (r * AS_STRIDE + c16 * 8) * 2,
                  g_Ah + (size_t)(mb0 * 128 + r) * F + c16 * 8);
    }
    asm volatile("cp.async.commit_group;");
    if (tid < 128) { csum_s[tid] = 0.f; csq_s[tid] = 0.f; }
    asm volatile("cp.async.wait_group 0;");
    __syncthreads();

    float csum_r[8], csq_r[8];
#pragma unroll
    for (int j = 0; j < 8; j++) { csum_r[j] = 0.f; csq_r[j] = 0.f; }

    int buf = 0;
    for (int mb = mb0; mb < MBLK; mb += GY) {
        int mbn = mb + GY;
        // sync 1: epilogue reads of C(t-1) (in A[buf^1]) are done across the CTA
        __syncthreads();
        if (mbn < MBLK) {
#pragma unroll
            for (int it = 0; it < 8; it++) {
                int idx = it * 256 + tid;
                int r = idx >> 4, c16 = idx & 15;
                cpasync16(a_sb[buf ^ 1] + (r * AS_STRIDE + c16 * 8) * 2,
                          g_Ah + (size_t)(mbn * 128 + r) * F + c16 * 8);
            }
            asm volatile("cp.async.commit_group;");
            asm volatile("cp.async.wait_group 1;");
        } else {
            asm volatile("cp.async.wait_group 0;");
        }
        // sync 2: A(t) visible to all threads
        __syncthreads();

        float c[4][4][4];
#pragma unroll
        for (int i = 0; i < 4; i++)
#pragma unroll
            for (int j = 0; j < 4; j++)
#pragma unroll
                for (int q = 0; q < 4; q++) c[i][j][q] = 0.f;

        uint32_t a_cur = a_sb[buf];
#pragma unroll
        for (int ks = 0; ks < 8; ks++) {
            uint32_t a[4][4], b[4][2];
#pragma unroll
            for (int mi = 0; mi < 4; mi++) {
                int row = wm * 64 + mi * 16 + (lane & 15);
                int kof = ks * 16 + ((lane >> 4) << 3);
                ldsm_x4(a[mi][0], a[mi][1], a[mi][2], a[mi][3],
                        a_cur + (row * AS_STRIDE + kof) * 2);
            }
#pragma unroll
            for (int hb = 0; hb < 2; hb++) {
                int krow = ks * 16 + (lane & 15);
                int ncol = wn * 32 + hb * 16 + ((lane >> 4) << 3);
                ldsm_x4_t(b[2 * hb][0], b[2 * hb][1], b[2 * hb + 1][0], b[2 * hb + 1][1],
                          b_sb + (krow * AS_STRIDE + ncol) * 2);
            }
#pragma unroll
            for (int mi = 0; mi < 4; mi++)
#pragma unroll
                for (int ni = 0; ni < 4; ni++)
                    mma16816(c[mi][ni], a[mi], b[ni]);
        }
        // sync 3: all warps done reading A[buf] -> recycle it as C staging
        __syncthreads();

        __half* Cs = (__half*)(sm + (buf ? SM_A1 : SM_A0));
#pragma unroll
        for (int mi = 0; mi < 4; mi++) {
#pragma unroll
            for (int ni = 0; ni < 4; ni++) {
                int row0 = wm * 64 + mi * 16 + gid;
                int col = wn * 32 + ni * 8 + tig * 2;
                *reinterpret_cast<__half2*>(&Cs[row0 * CS_STRIDE + col]) =
                    __floats2half2_rn(c[mi][ni][0], c[mi][ni][1]);
                *reinterpret_cast<__half2*>(&Cs[(row0 + 8) * CS_STRIDE + col]) =
                    __floats2half2_rn(c[mi][ni][2], c[mi][ni][3]);
                csum_r[ni * 2]     += c[mi][ni][0] + c[mi][ni][2];
                csum_r[ni * 2 + 1] += c[mi][ni][1] + c[mi][ni][3];
                csq_r[ni * 2]      += c[mi][ni][0] * c[mi][ni][0] + c[mi][ni][2] * c[mi][ni][2];
                csq_r[ni * 2 + 1]  += c[mi][ni][1] * c[mi][ni][1] + c[mi][ni][3] * c[mi][ni][3];
            }
        }
        __syncwarp();
        // store own 64x32 region: 8 passes, 4 lanes per row (16B each = 64B/row)
#pragma unroll
        for (int p = 0; p < 8; p++) {
            int rl = wm * 64 + p * 8 + (lane >> 2);
            int seg = lane & 3;
            int m = mb * 128 + rl;
            if (m < NE) {
                *reinterpret_cast<uint4*>(raw_row(m) + n0 + wn * 32 + seg * 8) =
                    *reinterpret_cast<const uint4*>(&Cs[rl * CS_STRIDE + wn * 32 + seg * 8]);
            }
        }
        buf ^= 1;
    }

    // ---- per-CTA stats reduction -> global ----
    __syncthreads();
#pragma unroll
    for (int ni = 0; ni < 4; ni++) {
#pragma unroll
        for (int t = 0; t < 2; t++) {
            int col = wn * 32 + ni * 8 + tig * 2 + t;
            atomicAdd(&csum_s[col], csum_r[ni * 2 + t]);
            atomicAdd(&csq_s[col],  csq_r[ni * 2 + t]);
        }
    }
    __syncthreads();
    if (tid < 128) {
        atomicAdd(&g_colsum[n0 + tid], csum_s[tid]);
        atomicAdd(&g_colsq[n0 + tid],  csq_s[tid]);
    }
}

// ---------------- BN coefficients ----------------
__global__ void k_bncoef(const float* __restrict__ gamma, const float* __restrict__ beta) {
    int i = blockIdx.x * 256 + threadIdx.x;
    if (i < DD) {
        float mu  = g_colsum[i] * (1.0f / NE);
        float var = g_colsq[i] * (1.0f / NE) - mu * mu;
        float a = gamma[i] * rsqrtf(var + EPSV);
        g_a[i] = a;
        g_c[i] = beta[i] - mu * a;
    }
}

// ---------------- message + scatter: agg[dst] += x[src] . (a*raw + c) -------------
__global__ __launch_bounds__(256) void k_msg(const float* __restrict__ x0,
                                             const int* __restrict__ ei,
                                             int first) {
    __shared__ __align__(16) float a_s[DD];
    __shared__ __align__(16) float c_s[DD];
    __shared__ float xs[8][D];

    const float* __restrict__ x = first ? x0 : (const float*)g_node;
    int tid = threadIdx.x;
    for (int i = tid * 4; i < DD; i += 1024) {
        *reinterpret_cast<float4*>(&a_s[i]) = *reinterpret_cast<const float4*>(&g_a[i]);
        *reinterpret_cast<float4*>(&c_s[i]) = *reinterpret_cast<const float4*>(&g_c[i]);
    }
    __syncthreads();

    int warp = tid >> 5, lane = tid & 31;
    int gw = blockIdx.x * 8 + warp;
    int k = lane * 2;

    for (int e = gw; e < NE; e += gridDim.x * 8) {
        int src = ei[e];
        int dst = ei[NE + e];
        xs[warp][lane]      = x[src * D + lane];
        xs[warp][lane + 32] = x[src * D + lane + 32];
        __syncwarp();

        const __half* rp = raw_row(e);
        float acc0 = 0.f, acc1 = 0.f;
#pragma unroll
        for (int d = 0; d < D; d++) {
            __half2 h = *reinterpret_cast<const __half2*>(rp + d * D + k);
            float2 r = __half22float2(h);
            float xv = xs[warp][d];
            int i0 = d * D + k;
            acc0 = fmaf(xv, fmaf(a_s[i0],     r.x, c_s[i0]),     acc0);
            acc1 = fmaf(xv, fmaf(a_s[i0 + 1], r.y, c_s[i0 + 1]), acc1);
        }
        atomicAdd(&g_agg[dst * D + k],     acc0);
        atomicAdd(&g_agg[dst * D + k + 1], acc1);
        __syncwarp();
    }
}

// ---------------- fused GRU: xin inline + GEMVs in SMEM + gates + acc/out ---------
#define GRU_SMEM (2048 * 4 * 2 + 32 * 192 * 4 * 2)   // 65536 B
__global__ __launch_bounds__(192) void k_gru(const float* __restrict__ x0,
                                             const float* __restrict__ Wih,
                                             const float* __restrict__ Whh,
                                             const float* __restrict__ b_ih,
                                             const float* __restrict__ b_hh,
                                             const float* __restrict__ bias,
                                             float* __restrict__ out,
                                             int first, int last) {
    extern __shared__ __align__(16) unsigned char smg[];
    float* xs   = (float*)smg;
    float* hs   = xs + 2048;
    float* gi_s = hs + 2048;
    float* gh_s = gi_s + 32 * 192;

    const float* __restrict__ h = first ? x0 : (const float*)g_node;
    int tid = threadIdx.x;
    int base = blockIdx.x * 32;

    // stage: xin = relu(agg*inv + bias) computed inline; agg re-zeroed
    for (int f4 = tid; f4 < 512; f4 += 192) {
        int nb = base + (f4 >> 4);
        int c4 = (f4 & 15) * 4;
        float4 v = make_float4(0.f, 0.f, 0.f, 0.f), w = v;
        if (nb < NN) {
            float4 ag = *reinterpret_cast<const float4*>(&g_agg[nb * D + c4]);
            float iv = g_inv[nb];
            v.x = fmaxf(fmaf(ag.x, iv, bias[c4 + 0]), 0.f);
            v.y = fmaxf(fmaf(ag.y, iv, bias[c4 + 1]), 0.f);
            v.z = fmaxf(fmaf(ag.z, iv, bias[c4 + 2]), 0.f);
            v.w = fmaxf(fmaf(ag.w, iv, bias[c4 + 3]), 0.f);
            *reinterpret_cast<float4*>(&g_agg[nb * D + c4]) = make_float4(0.f, 0.f, 0.f, 0.f);
            w = *reinterpret_cast<const float4*>(&h[nb * D + c4]);
        }
        *reinterpret_cast<float4*>(&xs[f4 * 4]) = v;
        *reinterpret_cast<float4*>(&hs[f4 * 4]) = w;
    }
    __syncthreads();

    {
        float4 wr[16];
#pragma unroll
        for (int q = 0; q < 16; q++) wr[q] = reinterpret_cast<const float4*>(Wih)[tid * 16 + q];
        for (int nn = 0; nn < 32; nn++) {
            float acc = 0.f;
#pragma unroll
            for (int q = 0; q < 16; q++) {
                float4 xv = *reinterpret_cast<float4*>(&xs[nn * D + q * 4]);
                float4 wv = wr[q];
                acc = fmaf(xv.x, wv.x, acc); acc = fmaf(xv.y, wv.y, acc);
                acc = fmaf(xv.z, wv.z, acc); acc = fmaf(xv.w, wv.w, acc);
            }
            gi_s[nn * 192 + tid] = acc;
        }
#pragma unroll
        for (int q = 0; q < 16; q++) wr[q] = reinterpret_cast<const float4*>(Whh)[tid * 16 + q];
        for (int nn = 0; nn < 32; nn++) {
            float acc = 0.f;
#pragma unroll
            for (int q = 0; q < 16; q++) {
                float4 xv = *reinterpret_cast<float4*>(&hs[nn * D + q * 4]);
                float4 wv = wr[q];
                acc = fmaf(xv.x, wv.x, acc); acc = fmaf(xv.y, wv.y, acc);
                acc = fmaf(xv.z, wv.z, acc); acc = fmaf(xv.w, wv.w, acc);
            }
            gh_s[nn * 192 + tid] = acc;
        }
    }
    __syncthreads();

    for (int i = tid; i < 2048; i += 192) {
        int gidx = base * D + i;
        if (gidx >= NN * D) break;
        int nl = i >> 6, j = i & 63;

        float ir = gi_s[nl * 192 + j]       + b_ih[j];
        float iz = gi_s[nl * 192 + 64 + j]  + b_ih[64 + j];
        float in = gi_s[nl * 192 + 128 + j] + b_ih[128 + j];
        float hr = gh_s[nl * 192 + j]       + b_hh[j];
        float hz = gh_s[nl * 192 + 64 + j]  + b_hh[64 + j];
        float hn = gh_s[nl * 192 + 128 + j] + b_hh[128 + j];

        float r = 1.0f / (1.0f + expf(-(ir + hr)));
        float z = 1.0f / (1.0f + expf(-(iz + hz)));
        float nv = tanhf(fmaf(r, hn, in));

        float hold = hs[i];
        float hnew = fmaf(z, hold - nv, nv);   // (1-z)*n + z*h

        if (last) {
            out[gidx] = (g_acc[gidx] + hold + hnew) * 0.25f + x0[gidx];
        } else {
            if (first) g_acc[gidx] = hold;
            else       g_acc[gidx] += hold;
            g_node[gidx] = hnew;
        }
    }
}

// ---------------- launcher ----------------
extern "C" void kernel_launch(void* const* d_in, const int* in_sizes, int n_in,
                              void* d_out, int out_size) {
    const float* node   = (const float*)d_in[0];
    const int*   ei     = (const int*)d_in[1];     // int32 (JAX x64 disabled)
    const float* edge   = (const float*)d_in[2];
    const float* W_edge = (const float*)d_in[3];
    const float* gamma  = (const float*)d_in[4];
    const float* beta   = (const float*)d_in[5];
    const float* bias   = (const float*)d_in[6];
    const float* W_ih   = (const float*)d_in[7];
    const float* W_hh   = (const float*)d_in[8];
    const float* b_ih   = (const float*)d_in[9];
    const float* b_hh   = (const float*)d_in[10];
    float* out = (float*)d_out;

    cudaFuncSetAttribute(k_gemm_edge, cudaFuncAttributeMaxDynamicSharedMemorySize, GEMM_SMEM);
    cudaFuncSetAttribute(k_gru, cudaFuncAttributeMaxDynamicSharedMemorySize, GRU_SMEM);

    int nelem_blocks = (NN * D + 255) / 256;
    k_zero_pre<<<nelem_blocks, 256>>>();
    k_count<<<(NE + 255) / 256, 256>>>(ei);
    k_inv<<<196, 256>>>();

    k_toh_A<<<(NEPAD * F / 8 + 255) / 256, 256>>>(edge);
    k_toh_B<<<(F * DD / 8 + 255) / 256, 256>>>(W_edge);

    dim3 gg(DD / 128, GY);
    k_gemm_edge<<<gg, 256, GEMM_SMEM>>>();
    k_bncoef<<<16, 256>>>(gamma, beta);

    // only 3 propagation steps needed: out = x0 + mean(node_0..node_3);
    // the reference's 4th GRU update is dead code.
    for (int s = 0; s < 3; s++) {
        int first = (s == 0) ? 1 : 0;
        int last = (s == 2) ? 1 : 0;
        k_msg<<<1184, 256>>>(node, ei, first);
        k_gru<<<(NN + 31) / 32, 192, GRU_SMEM>>>(node, W_ih, W_hh, b_ih, b_hh, bias, out, first, last);
    }
}

// round 15
// speedup vs baseline: 1.1845x; 1.0554x over previous
#include <cuda_runtime.h>
#include <cuda_fp16.h>
#include <math.h>
#include <stdint.h>

#define NN 50000
#define NE 100000
#define D  64
#define F  128
#define DD 4096
#define EPSV 1e-5f
#define ECHUNK 25600
#define NEPAD 100096
#define MBLK 782       // NEPAD / 128
#define GY 74          // 32*74 = 2368 CTAs = 8 waves of 296 (2 CTAs/SM)

// ---------------- scratch (static device globals; no runtime alloc) ----------------
__device__ __align__(16) __half g_raw0[(size_t)ECHUNK * DD];
__device__ __align__(16) __half g_raw1[(size_t)ECHUNK * DD];
__device__ __align__(16) __half g_raw2[(size_t)ECHUNK * DD];
__device__ __align__(16) __half g_raw3[(size_t)ECHUNK * DD];

__device__ __forceinline__ __half* raw_row(int e) {
    int c = e / ECHUNK;
    int r = e - c * ECHUNK;
    __half* base = (c == 0) ? g_raw0 : (c == 1) ? g_raw1 : (c == 2) ? g_raw2 : g_raw3;
    return base + (size_t)r * DD;
}

__device__ __align__(16) __half g_Ah[(size_t)NEPAD * F];   // 25.6 MB
__device__ __align__(16) __half g_Bh[(size_t)F * DD];      // 1 MB  [k][n]

__device__ __align__(16) float g_colsum[DD];
__device__ __align__(16) float g_colsq[DD];
__device__ __align__(16) float g_a[DD];
__device__ __align__(16) float g_c[DD];
__device__ __align__(16) float g_cnt[NN];
__device__ __align__(16) float g_inv[NN];
__device__ __align__(16) float g_agg[NN * D];
__device__ __align__(16) float g_node[NN * D];
__device__ __align__(16) float g_acc[NN * D];

struct alignas(8) H4 { __half2 x, y; };

// ---------------- zero / count helpers ----------------
__global__ void k_zero_pre() {
    int i = blockIdx.x * 256 + threadIdx.x;
    if (i < DD) { g_colsum[i] = 0.f; g_colsq[i] = 0.f; }
    if (i < NN) g_cnt[i] = 0.f;
    if (i < NN * D) g_agg[i] = 0.f;
}

__global__ void k_count(const int* __restrict__ ei) {
    int e = blockIdx.x * 256 + threadIdx.x;
    if (e < NE) atomicAdd(&g_cnt[ei[NE + e]], 1.0f);
}

__global__ void k_inv() {
    int i = blockIdx.x * 256 + threadIdx.x;
    if (i < NN) g_inv[i] = 1.0f / fmaxf(g_cnt[i], 1.0f);
}

// ---------------- fp32 -> fp16 pre-conversion ----------------
__global__ void k_toh_A(const float* __restrict__ A) {
    int i = blockIdx.x * 256 + threadIdx.x;   // one per 8 elems
    if (i >= NEPAD * F / 8) return;
    int r = i / (F / 8);
    H4 h0, h1;
    if (r < NE) {
        const float4* s = reinterpret_cast<const float4*>(A) + (size_t)i * 2;
        float4 v0 = s[0], v1 = s[1];
        h0.x = __floats2half2_rn(v0.x, v0.y); h0.y = __floats2half2_rn(v0.z, v0.w);
        h1.x = __floats2half2_rn(v1.x, v1.y); h1.y = __floats2half2_rn(v1.z, v1.w);
    } else {
        h0.x = h0.y = h1.x = h1.y = __floats2half2_rn(0.f, 0.f);
    }
    H4* d = reinterpret_cast<H4*>(g_Ah) + (size_t)i * 2;
    d[0] = h0; d[1] = h1;
}

__global__ void k_toh_B(const float* __restrict__ B) {
    int i = blockIdx.x * 256 + threadIdx.x;
    if (i >= F * DD / 8) return;
    const float4* s = reinterpret_cast<const float4*>(B) + (size_t)i * 2;
    float4 v0 = s[0], v1 = s[1];
    H4 h0, h1;
    h0.x = __floats2half2_rn(v0.x, v0.y); h0.y = __floats2half2_rn(v0.z, v0.w);
    h1.x = __floats2half2_rn(v1.x, v1.y); h1.y = __floats2half2_rn(v1.z, v1.w);
    H4* d = reinterpret_cast<H4*>(g_Bh) + (size_t)i * 2;
    d[0] = h0; d[1] = h1;
}

// ---------------- tensor-core GEMM helpers ----------------
__device__ __forceinline__ void ldsm_x4(uint32_t& r0, uint32_t& r1, uint32_t& r2, uint32_t& r3,
                                        uint32_t addr) {
    asm volatile("ldmatrix.sync.aligned.m8n8.x4.shared.b16 {%0,%1,%2,%3}, [%4];"
                 : "=r"(r0), "=r"(r1), "=r"(r2), "=r"(r3) : "r"(addr));
}
__device__ __forceinline__ void ldsm_x4_t(uint32_t& r0, uint32_t& r1, uint32_t& r2, uint32_t& r3,
                                          uint32_t addr) {
    asm volatile("ldmatrix.sync.aligned.m8n8.x4.trans.shared.b16 {%0,%1,%2,%3}, [%4];"
                 : "=r"(r0), "=r"(r1), "=r"(r2), "=r"(r3) : "r"(addr));
}
__device__ __forceinline__ void mma16816(float* c, const uint32_t* a, const uint32_t* b) {
    asm volatile(
        "mma.sync.aligned.m16n8k16.row.col.f32.f16.f16.f32 "
        "{%0,%1,%2,%3}, {%4,%5,%6,%7}, {%8,%9}, {%0,%1,%2,%3};"
        : "+f"(c[0]), "+f"(c[1]), "+f"(c[2]), "+f"(c[3])
        : "r"(a[0]), "r"(a[1]), "r"(a[2]), "r"(a[3]), "r"(b[0]), "r"(b[1]));
}
__device__ __forceinline__ void cpasync16(uint32_t smem, const void* gptr) {
    asm volatile("cp.async.cg.shared.global [%0], [%1], 16;" :: "r"(smem), "l"(gptr));
}

// ---------------- big GEMM: raw = A_h[NE,128] @ B_h[128,4096] + col stats ----
// Persistent n-strip CTAs at 2 CTAs/SM. 8 warps (2m x 4n), warp tile 64x32.
// B resident in SMEM (ldsm per ks); A double-buffered cp.async; C staged into
// the DEAD A buffer. Regs <= 128. (unchanged from R14)
#define AS_STRIDE 136
#define CS_STRIDE 136
#define TILE_B (128 * 136 * 2)          // 34816 B
#define SM_A0 0
#define SM_A1 TILE_B
#define SM_B  (TILE_B * 2)
#define GEMM_SMEM (TILE_B * 3 + 1024)   // 105472 B -> 2 CTAs/SM
__global__ __launch_bounds__(256, 2) void k_gemm_edge() {
    extern __shared__ __align__(16) unsigned char sm[];
    float* csum_s = (float*)(sm + TILE_B * 3);
    float* csq_s  = csum_s + 128;

    int tid = threadIdx.x;
    int warp = tid >> 5, lane = tid & 31;
    int wm = warp & 1, wn = warp >> 1;
    int gid = lane >> 2, tig = lane & 3;
    int n0 = blockIdx.x * 128;
    int mb0 = blockIdx.y;

    uint32_t sb = (uint32_t)__cvta_generic_to_shared(sm);
    uint32_t a_sb[2] = { sb + SM_A0, sb + SM_A1 };
    uint32_t b_sb = sb + SM_B;

#pragma unroll
    for (int it = 0; it < 8; it++) {
        int idx = it * 256 + tid;
        int r = idx >> 4, c16 = idx & 15;
        cpasync16(b_sb + (r * AS_STRIDE + c16 * 8) * 2,
                  g_Bh + (size_t)r * DD + n0 + c16 * 8);
    }
#pragma unroll
    for (int it = 0; it < 8; it++) {
        int idx = it * 256 + tid;
        int r = idx >> 4, c16 = idx & 15;
        cpasync16(a_sb[0] + (r * AS_STRIDE + c16 * 8) * 2,
                  g_Ah + (size_t)(mb0 * 128 + r) * F + c16 * 8);
    }
    asm volatile("cp.async.commit_group;");
    if (tid < 128) { csum_s[tid] = 0.f; csq_s[tid] = 0.f; }
    asm volatile("cp.async.wait_group 0;");
    __syncthreads();

    float csum_r[8], csq_r[8];
#pragma unroll
    for (int j = 0; j < 8; j++) { csum_r[j] = 0.f; csq_r[j] = 0.f; }

    int buf = 0;
    for (int mb = mb0; mb < MBLK; mb += GY) {
        int mbn = mb + GY;
        __syncthreads();
        if (mbn < MBLK) {
#pragma unroll
            for (int it = 0; it < 8; it++) {
                int idx = it * 256 + tid;
                int r = idx >> 4, c16 = idx & 15;
                cpasync16(a_sb[buf ^ 1] + (r * AS_STRIDE + c16 * 8) * 2,
                          g_Ah + (size_t)(mbn * 128 + r) * F + c16 * 8);
            }
            asm volatile("cp.async.commit_group;");
            asm volatile("cp.async.wait_group 1;");
        } else {
            asm volatile("cp.async.wait_group 0;");
        }
        __syncthreads();

        float c[4][4][4];
#pragma unroll
        for (int i = 0; i < 4; i++)
#pragma unroll
            for (int j = 0; j < 4; j++)
#pragma unroll
                for (int q = 0; q < 4; q++) c[i][j][q] = 0.f;

        uint32_t a_cur = a_sb[buf];
#pragma unroll
        for (int ks = 0; ks < 8; ks++) {
            uint32_t a[4][4], b[4][2];
#pragma unroll
            for (int mi = 0; mi < 4; mi++) {
                int row = wm * 64 + mi * 16 + (lane & 15);
                int kof = ks * 16 + ((lane >> 4) << 3);
                ldsm_x4(a[mi][0], a[mi][1], a[mi][2], a[mi][3],
                        a_cur + (row * AS_STRIDE + kof) * 2);
            }
#pragma unroll
            for (int hb = 0; hb < 2; hb++) {
                int krow = ks * 16 + (lane & 15);
                int ncol = wn * 32 + hb * 16 + ((lane >> 4) << 3);
                ldsm_x4_t(b[2 * hb][0], b[2 * hb][1], b[2 * hb + 1][0], b[2 * hb + 1][1],
                          b_sb + (krow * AS_STRIDE + ncol) * 2);
            }
#pragma unroll
            for (int mi = 0; mi < 4; mi++)
#pragma unroll
                for (int ni = 0; ni < 4; ni++)
                    mma16816(c[mi][ni], a[mi], b[ni]);
        }
        __syncthreads();

        __half* Cs = (__half*)(sm + (buf ? SM_A1 : SM_A0));
#pragma unroll
        for (int mi = 0; mi < 4; mi++) {
#pragma unroll
            for (int ni = 0; ni < 4; ni++) {
                int row0 = wm * 64 + mi * 16 + gid;
                int col = wn * 32 + ni * 8 + tig * 2;
                *reinterpret_cast<__half2*>(&Cs[row0 * CS_STRIDE + col]) =
                    __floats2half2_rn(c[mi][ni][0], c[mi][ni][1]);
                *reinterpret_cast<__half2*>(&Cs[(row0 + 8) * CS_STRIDE + col]) =
                    __floats2half2_rn(c[mi][ni][2], c[mi][ni][3]);
                csum_r[ni * 2]     += c[mi][ni][0] + c[mi][ni][2];
                csum_r[ni * 2 + 1] += c[mi][ni][1] + c[mi][ni][3];
                csq_r[ni * 2]      += c[mi][ni][0] * c[mi][ni][0] + c[mi][ni][2] * c[mi][ni][2];
                csq_r[ni * 2 + 1]  += c[mi][ni][1] * c[mi][ni][1] + c[mi][ni][3] * c[mi][ni][3];
            }
        }
        __syncwarp();
#pragma unroll
        for (int p = 0; p < 8; p++) {
            int rl = wm * 64 + p * 8 + (lane >> 2);
            int seg = lane & 3;
            int m = mb * 128 + rl;
            if (m < NE) {
                *reinterpret_cast<uint4*>(raw_row(m) + n0 + wn * 32 + seg * 8) =
                    *reinterpret_cast<const uint4*>(&Cs[rl * CS_STRIDE + wn * 32 + seg * 8]);
            }
        }
        buf ^= 1;
    }

    __syncthreads();
#pragma unroll
    for (int ni = 0; ni < 4; ni++) {
#pragma unroll
        for (int t = 0; t < 2; t++) {
            int col = wn * 32 + ni * 8 + tig * 2 + t;
            atomicAdd(&csum_s[col], csum_r[ni * 2 + t]);
            atomicAdd(&csq_s[col],  csq_r[ni * 2 + t]);
        }
    }
    __syncthreads();
    if (tid < 128) {
        atomicAdd(&g_colsum[n0 + tid], csum_s[tid]);
        atomicAdd(&g_colsq[n0 + tid],  csq_s[tid]);
    }
}

// ---------------- BN coefficients ----------------
__global__ void k_bncoef(const float* __restrict__ gamma, const float* __restrict__ beta) {
    int i = blockIdx.x * 256 + threadIdx.x;
    if (i < DD) {
        float mu  = g_colsum[i] * (1.0f / NE);
        float var = g_colsq[i] * (1.0f / NE) - mu * mu;
        float a = gamma[i] * rsqrtf(var + EPSV);
        g_a[i] = a;
        g_c[i] = beta[i] - mu * a;
    }
}

// ---------------- message + scatter: agg[dst] += x[src] . (a*raw + c) -------------
// warp-per-edge; 16B raw loads; a/c pre-packed half2 in SMEM (HFMA2); fp32
// x-weighted accumulate; butterfly reduce -> 8 lanes x 8 atomics.
#define ACS 36   // half2 stride per d-row (32 + 4 pad: 144B, bank-rotated, 16B-aligned)
__global__ __launch_bounds__(256) void k_msg(const float* __restrict__ x0,
                                             const int* __restrict__ ei,
                                             int first) {
    __shared__ __align__(16) __half2 a2_s[64 * ACS];
    __shared__ __align__(16) __half2 c2_s[64 * ACS];
    __shared__ float xs[8][D];

    const float* __restrict__ x = first ? x0 : (const float*)g_node;
    int tid = threadIdx.x;
    for (int i = tid; i < 2048; i += 256) {
        int d = i >> 5, cc = i & 31;
        float2 av = *reinterpret_cast<const float2*>(&g_a[d * 64 + cc * 2]);
        float2 cv = *reinterpret_cast<const float2*>(&g_c[d * 64 + cc * 2]);
        a2_s[d * ACS + cc] = __floats2half2_rn(av.x, av.y);
        c2_s[d * ACS + cc] = __floats2half2_rn(cv.x, cv.y);
    }
    __syncthreads();

    int warp = tid >> 5, lane = tid & 31;
    int cq = lane & 7, dr = lane >> 3;
    int gw = blockIdx.x * 8 + warp;

    for (int e = gw; e < NE; e += gridDim.x * 8) {
        int src = ei[e];
        int dst = ei[NE + e];
        xs[warp][lane]      = x[src * D + lane];
        xs[warp][lane + 32] = x[src * D + lane + 32];
        __syncwarp();

        const __half* rp = raw_row(e);
        float acc[8];
#pragma unroll
        for (int j = 0; j < 8; j++) acc[j] = 0.f;

#pragma unroll
        for (int it = 0; it < 16; it++) {
            int d = it * 4 + dr;
            uint4 rv = *reinterpret_cast<const uint4*>(rp + d * D + cq * 8);
            uint4 av = *reinterpret_cast<const uint4*>(&a2_s[d * ACS + cq * 4]);
            uint4 cv = *reinterpret_cast<const uint4*>(&c2_s[d * ACS + cq * 4]);
            float xv = xs[warp][d];
            const __half2* rh = reinterpret_cast<const __half2*>(&rv);
            const __half2* ah = reinterpret_cast<const __half2*>(&av);
            const __half2* ch = reinterpret_cast<const __half2*>(&cv);
#pragma unroll
            for (int p = 0; p < 4; p++) {
                __half2 m = __hfma2(ah[p], rh[p], ch[p]);
                float2 f = __half22float2(m);
                acc[p * 2]     = fmaf(xv, f.x, acc[p * 2]);
                acc[p * 2 + 1] = fmaf(xv, f.y, acc[p * 2 + 1]);
            }
        }
#pragma unroll
        for (int j = 0; j < 8; j++) {
            acc[j] += __shfl_down_sync(0xffffffffu, acc[j], 16);
            acc[j] += __shfl_down_sync(0xffffffffu, acc[j], 8);
        }
        if (lane < 8) {
            float* gp = &g_agg[dst * D + lane * 8];
#pragma unroll
            for (int j = 0; j < 8; j++) atomicAdd(gp + j, acc[j]);
        }
        __syncwarp();
    }
}

// ---------------- fused GRU: xin inline + GEMVs in SMEM + gates + acc/out ---------
#define GRU_SMEM (2048 * 4 * 2 + 32 * 192 * 4 * 2)   // 65536 B
__global__ __launch_bounds__(192) void k_gru(const float* __restrict__ x0,
                                             const float* __restrict__ Wih,
                                             const float* __restrict__ Whh,
                                             const float* __restrict__ b_ih,
                                             const float* __restrict__ b_hh,
                                             const float* __restrict__ bias,
                                             float* __restrict__ out,
                                             int first, int last) {
    extern __shared__ __align__(16) unsigned char smg[];
    float* xs   = (float*)smg;
    float* hs   = xs + 2048;
    float* gi_s = hs + 2048;
    float* gh_s = gi_s + 32 * 192;

    const float* __restrict__ h = first ? x0 : (const float*)g_node;
    int tid = threadIdx.x;
    int base = blockIdx.x * 32;

    for (int f4 = tid; f4 < 512; f4 += 192) {
        int nb = base + (f4 >> 4);
        int c4 = (f4 & 15) * 4;
        float4 v = make_float4(0.f, 0.f, 0.f, 0.f), w = v;
        if (nb < NN) {
            float4 ag = *reinterpret_cast<const float4*>(&g_agg[nb * D + c4]);
            float iv = g_inv[nb];
            v.x = fmaxf(fmaf(ag.x, iv, bias[c4 + 0]), 0.f);
            v.y = fmaxf(fmaf(ag.y, iv, bias[c4 + 1]), 0.f);
            v.z = fmaxf(fmaf(ag.z, iv, bias[c4 + 2]), 0.f);
            v.w = fmaxf(fmaf(ag.w, iv, bias[c4 + 3]), 0.f);
            *reinterpret_cast<float4*>(&g_agg[nb * D + c4]) = make_float4(0.f, 0.f, 0.f, 0.f);
            w = *reinterpret_cast<const float4*>(&h[nb * D + c4]);
        }
        *reinterpret_cast<float4*>(&xs[f4 * 4]) = v;
        *reinterpret_cast<float4*>(&hs[f4 * 4]) = w;
    }
    __syncthreads();

    {
        float4 wr[16];
#pragma unroll
        for (int q = 0; q < 16; q++) wr[q] = reinterpret_cast<const float4*>(Wih)[tid * 16 + q];
        for (int nn = 0; nn < 32; nn++) {
            float acc = 0.f;
#pragma unroll
            for (int q = 0; q < 16; q++) {
                float4 xv = *reinterpret_cast<float4*>(&xs[nn * D + q * 4]);
                float4 wv = wr[q];
                acc = fmaf(xv.x, wv.x, acc); acc = fmaf(xv.y, wv.y, acc);
                acc = fmaf(xv.z, wv.z, acc); acc = fmaf(xv.w, wv.w, acc);
            }
            gi_s[nn * 192 + tid] = acc;
        }
#pragma unroll
        for (int q = 0; q < 16; q++) wr[q] = reinterpret_cast<const float4*>(Whh)[tid * 16 + q];
        for (int nn = 0; nn < 32; nn++) {
            float acc = 0.f;
#pragma unroll
            for (int q = 0; q < 16; q++) {
                float4 xv = *reinterpret_cast<float4*>(&hs[nn * D + q * 4]);
                float4 wv = wr[q];
                acc = fmaf(xv.x, wv.x, acc); acc = fmaf(xv.y, wv.y, acc);
                acc = fmaf(xv.z, wv.z, acc); acc = fmaf(xv.w, wv.w, acc);
            }
            gh_s[nn * 192 + tid] = acc;
        }
    }
    __syncthreads();

    for (int i = tid; i < 2048; i += 192) {
        int gidx = base * D + i;
        if (gidx >= NN * D) break;
        int nl = i >> 6, j = i & 63;

        float ir = gi_s[nl * 192 + j]       + b_ih[j];
        float iz = gi_s[nl * 192 + 64 + j]  + b_ih[64 + j];
        float in = gi_s[nl * 192 + 128 + j] + b_ih[128 + j];
        float hr = gh_s[nl * 192 + j]       + b_hh[j];
        float hz = gh_s[nl * 192 + 64 + j]  + b_hh[64 + j];
        float hn = gh_s[nl * 192 + 128 + j] + b_hh[128 + j];

        float r = 1.0f / (1.0f + expf(-(ir + hr)));
        float z = 1.0f / (1.0f + expf(-(iz + hz)));
        float nv = tanhf(fmaf(r, hn, in));

        float hold = hs[i];
        float hnew = fmaf(z, hold - nv, nv);   // (1-z)*n + z*h

        if (last) {
            out[gidx] = (g_acc[gidx] + hold + hnew) * 0.25f + x0[gidx];
        } else {
            if (first) g_acc[gidx] = hold;
            else       g_acc[gidx] += hold;
            g_node[gidx] = hnew;
        }
    }
}

// ---------------- launcher ----------------
extern "C" void kernel_launch(void* const* d_in, const int* in_sizes, int n_in,
                              void* d_out, int out_size) {
    const float* node   = (const float*)d_in[0];
    const int*   ei     = (const int*)d_in[1];     // int32 (JAX x64 disabled)
    const float* edge   = (const float*)d_in[2];
    const float* W_edge = (const float*)d_in[3];
    const float* gamma  = (const float*)d_in[4];
    const float* beta   = (const float*)d_in[5];
    const float* bias   = (const float*)d_in[6];
    const float* W_ih   = (const float*)d_in[7];
    const float* W_hh   = (const float*)d_in[8];
    const float* b_ih   = (const float*)d_in[9];
    const float* b_hh   = (const float*)d_in[10];
    float* out = (float*)d_out;

    cudaFuncSetAttribute(k_gemm_edge, cudaFuncAttributeMaxDynamicSharedMemorySize, GEMM_SMEM);
    cudaFuncSetAttribute(k_gru, cudaFuncAttributeMaxDynamicSharedMemorySize, GRU_SMEM);

    int nelem_blocks = (NN * D + 255) / 256;
    k_zero_pre<<<nelem_blocks, 256>>>();
    k_count<<<(NE + 255) / 256, 256>>>(ei);
    k_inv<<<196, 256>>>();

    k_toh_A<<<(NEPAD * F / 8 + 255) / 256, 256>>>(edge);
    k_toh_B<<<(F * DD / 8 + 255) / 256, 256>>>(W_edge);

    dim3 gg(DD / 128, GY);
    k_gemm_edge<<<gg, 256, GEMM_SMEM>>>();
    k_bncoef<<<16, 256>>>(gamma, beta);

    // only 3 propagation steps needed: out = x0 + mean(node_0..node_3);
    // the reference's 4th GRU update is dead code.
    for (int s = 0; s < 3; s++) {
        int first = (s == 0) ? 1 : 0;
        int last = (s == 2) ? 1 : 0;
        k_msg<<<1184, 256>>>(node, ei, first);
        k_gru<<<(NN + 31) / 32, 192, GRU_SMEM>>>(node, W_ih, W_hh, b_ih, b_hh, bias, out, first, last);
    }
}

// round 16
// speedup vs baseline: 1.1922x; 1.0065x over previous
#include <cuda_runtime.h>
#include <cuda_fp16.h>
#include <math.h>
#include <stdint.h>

#define NN 50000
#define NE 100000
#define D  64
#define F  128
#define DD 4096
#define EPSV 1e-5f
#define ECHUNK 25600
#define NEPAD 100096
#define MBLK 782       // NEPAD / 128
#define GY 74          // 32*74 = 2368 CTAs = 8 waves of 296 (2 CTAs/SM)

// ---------------- scratch (static device globals; no runtime alloc) ----------------
__device__ __align__(16) __half g_raw0[(size_t)ECHUNK * DD];
__device__ __align__(16) __half g_raw1[(size_t)ECHUNK * DD];
__device__ __align__(16) __half g_raw2[(size_t)ECHUNK * DD];
__device__ __align__(16) __half g_raw3[(size_t)ECHUNK * DD];

__device__ __forceinline__ __half* raw_row(int e) {
    int c = e / ECHUNK;
    int r = e - c * ECHUNK;
    __half* base = (c == 0) ? g_raw0 : (c == 1) ? g_raw1 : (c == 2) ? g_raw2 : g_raw3;
    return base + (size_t)r * DD;
}

__device__ __align__(16) __half g_Ah[(size_t)NEPAD * F];   // 25.6 MB
__device__ __align__(16) __half g_Bh[(size_t)F * DD];      // 1 MB  [k][n]

__device__ __align__(16) float g_colsum[DD];
__device__ __align__(16) float g_colsq[DD];
__device__ __align__(16) float g_a[DD];
__device__ __align__(16) float g_c[DD];
__device__ __align__(16) float g_cnt[NN];
__device__ __align__(16) float g_inv[NN];
__device__ __align__(16) float g_agg[NN * D];
__device__ __align__(16) float g_node[NN * D];
__device__ __align__(16) float g_acc[NN * D];

struct alignas(8) H4 { __half2 x, y; };

// ---------------- zero / count helpers ----------------
__global__ void k_zero_pre() {
    int i = blockIdx.x * 256 + threadIdx.x;
    if (i < DD) { g_colsum[i] = 0.f; g_colsq[i] = 0.f; }
    if (i < NN) g_cnt[i] = 0.f;
    if (i < NN * D) g_agg[i] = 0.f;
}

__global__ void k_count(const int* __restrict__ ei) {
    int e = blockIdx.x * 256 + threadIdx.x;
    if (e < NE) atomicAdd(&g_cnt[ei[NE + e]], 1.0f);
}

__global__ void k_inv() {
    int i = blockIdx.x * 256 + threadIdx.x;
    if (i < NN) g_inv[i] = 1.0f / fmaxf(g_cnt[i], 1.0f);
}

// ---------------- fp32 -> fp16 pre-conversion ----------------
__global__ void k_toh_A(const float* __restrict__ A) {
    int i = blockIdx.x * 256 + threadIdx.x;   // one per 8 elems
    if (i >= NEPAD * F / 8) return;
    int r = i / (F / 8);
    H4 h0, h1;
    if (r < NE) {
        const float4* s = reinterpret_cast<const float4*>(A) + (size_t)i * 2;
        float4 v0 = s[0], v1 = s[1];
        h0.x = __floats2half2_rn(v0.x, v0.y); h0.y = __floats2half2_rn(v0.z, v0.w);
        h1.x = __floats2half2_rn(v1.x, v1.y); h1.y = __floats2half2_rn(v1.z, v1.w);
    } else {
        h0.x = h0.y = h1.x = h1.y = __floats2half2_rn(0.f, 0.f);
    }
    H4* d = reinterpret_cast<H4*>(g_Ah) + (size_t)i * 2;
    d[0] = h0; d[1] = h1;
}

__global__ void k_toh_B(const float* __restrict__ B) {
    int i = blockIdx.x * 256 + threadIdx.x;
    if (i >= F * DD / 8) return;
    const float4* s = reinterpret_cast<const float4*>(B) + (size_t)i * 2;
    float4 v0 = s[0], v1 = s[1];
    H4 h0, h1;
    h0.x = __floats2half2_rn(v0.x, v0.y); h0.y = __floats2half2_rn(v0.z, v0.w);
    h1.x = __floats2half2_rn(v1.x, v1.y); h1.y = __floats2half2_rn(v1.z, v1.w);
    H4* d = reinterpret_cast<H4*>(g_Bh) + (size_t)i * 2;
    d[0] = h0; d[1] = h1;
}

// ---------------- tensor-core GEMM helpers ----------------
__device__ __forceinline__ void ldsm_x4(uint32_t& r0, uint32_t& r1, uint32_t& r2, uint32_t& r3,
                                        uint32_t addr) {
    asm volatile("ldmatrix.sync.aligned.m8n8.x4.shared.b16 {%0,%1,%2,%3}, [%4];"
                 : "=r"(r0), "=r"(r1), "=r"(r2), "=r"(r3) : "r"(addr));
}
__device__ __forceinline__ void ldsm_x4_t(uint32_t& r0, uint32_t& r1, uint32_t& r2, uint32_t& r3,
                                          uint32_t addr) {
    asm volatile("ldmatrix.sync.aligned.m8n8.x4.trans.shared.b16 {%0,%1,%2,%3}, [%4];"
                 : "=r"(r0), "=r"(r1), "=r"(r2), "=r"(r3) : "r"(addr));
}
__device__ __forceinline__ void mma16816(float* c, const uint32_t* a, const uint32_t* b) {
    asm volatile(
        "mma.sync.aligned.m16n8k16.row.col.f32.f16.f16.f32 "
        "{%0,%1,%2,%3}, {%4,%5,%6,%7}, {%8,%9}, {%0,%1,%2,%3};"
        : "+f"(c[0]), "+f"(c[1]), "+f"(c[2]), "+f"(c[3])
        : "r"(a[0]), "r"(a[1]), "r"(a[2]), "r"(a[3]), "r"(b[0]), "r"(b[1]));
}
__device__ __forceinline__ void cpasync16(uint32_t smem, const void* gptr) {
    asm volatile("cp.async.cg.shared.global [%0], [%1], 16;" :: "r"(smem), "l"(gptr));
}

// ---------------- big GEMM: raw = A_h[NE,128] @ B_h[128,4096] + col stats ----
// (unchanged from R14/R15: persistent n-strips, 2 CTAs/SM, B in SMEM, A dbuf)
#define AS_STRIDE 136
#define CS_STRIDE 136
#define TILE_B (128 * 136 * 2)          // 34816 B
#define SM_A0 0
#define SM_A1 TILE_B
#define SM_B  (TILE_B * 2)
#define GEMM_SMEM (TILE_B * 3 + 1024)   // 105472 B -> 2 CTAs/SM
__global__ __launch_bounds__(256, 2) void k_gemm_edge() {
    extern __shared__ __align__(16) unsigned char sm[];
    float* csum_s = (float*)(sm + TILE_B * 3);
    float* csq_s  = csum_s + 128;

    int tid = threadIdx.x;
    int warp = tid >> 5, lane = tid & 31;
    int wm = warp & 1, wn = warp >> 1;
    int gid = lane >> 2, tig = lane & 3;
    int n0 = blockIdx.x * 128;
    int mb0 = blockIdx.y;

    uint32_t sb = (uint32_t)__cvta_generic_to_shared(sm);
    uint32_t a_sb[2] = { sb + SM_A0, sb + SM_A1 };
    uint32_t b_sb = sb + SM_B;

#pragma unroll
    for (int it = 0; it < 8; it++) {
        int idx = it * 256 + tid;
        int r = idx >> 4, c16 = idx & 15;
        cpasync16(b_sb + (r * AS_STRIDE + c16 * 8) * 2,
                  g_Bh + (size_t)r * DD + n0 + c16 * 8);
    }
#pragma unroll
    for (int it = 0; it < 8; it++) {
        int idx = it * 256 + tid;
        int r = idx >> 4, c16 = idx & 15;
        cpasync16(a_sb[0] + (r * AS_STRIDE + c16 * 8) * 2,
                  g_Ah + (size_t)(mb0 * 128 + r) * F + c16 * 8);
    }
    asm volatile("cp.async.commit_group;");
    if (tid < 128) { csum_s[tid] = 0.f; csq_s[tid] = 0.f; }
    asm volatile("cp.async.wait_group 0;");
    __syncthreads();

    float csum_r[8], csq_r[8];
#pragma unroll
    for (int j = 0; j < 8; j++) { csum_r[j] = 0.f; csq_r[j] = 0.f; }

    int buf = 0;
    for (int mb = mb0; mb < MBLK; mb += GY) {
        int mbn = mb + GY;
        __syncthreads();
        if (mbn < MBLK) {
#pragma unroll
            for (int it = 0; it < 8; it++) {
                int idx = it * 256 + tid;
                int r = idx >> 4, c16 = idx & 15;
                cpasync16(a_sb[buf ^ 1] + (r * AS_STRIDE + c16 * 8) * 2,
                          g_Ah + (size_t)(mbn * 128 + r) * F + c16 * 8);
            }
            asm volatile("cp.async.commit_group;");
            asm volatile("cp.async.wait_group 1;");
        } else {
            asm volatile("cp.async.wait_group 0;");
        }
        __syncthreads();

        float c[4][4][4];
#pragma unroll
        for (int i = 0; i < 4; i++)
#pragma unroll
            for (int j = 0; j < 4; j++)
#pragma unroll
                for (int q = 0; q < 4; q++) c[i][j][q] = 0.f;

        uint32_t a_cur = a_sb[buf];
#pragma unroll
        for (int ks = 0; ks < 8; ks++) {
            uint32_t a[4][4], b[4][2];
#pragma unroll
            for (int mi = 0; mi < 4; mi++) {
                int row = wm * 64 + mi * 16 + (lane & 15);
                int kof = ks * 16 + ((lane >> 4) << 3);
                ldsm_x4(a[mi][0], a[mi][1], a[mi][2], a[mi][3],
                        a_cur + (row * AS_STRIDE + kof) * 2);
            }
#pragma unroll
            for (int hb = 0; hb < 2; hb++) {
                int krow = ks * 16 + (lane & 15);
                int ncol = wn * 32 + hb * 16 + ((lane >> 4) << 3);
                ldsm_x4_t(b[2 * hb][0], b[2 * hb][1], b[2 * hb + 1][0], b[2 * hb + 1][1],
                          b_sb + (krow * AS_STRIDE + ncol) * 2);
            }
#pragma unroll
            for (int mi = 0; mi < 4; mi++)
#pragma unroll
                for (int ni = 0; ni < 4; ni++)
                    mma16816(c[mi][ni], a[mi], b[ni]);
        }
        __syncthreads();

        __half* Cs = (__half*)(sm + (buf ? SM_A1 : SM_A0));
#pragma unroll
        for (int mi = 0; mi < 4; mi++) {
#pragma unroll
            for (int ni = 0; ni < 4; ni++) {
                int row0 = wm * 64 + mi * 16 + gid;
                int col = wn * 32 + ni * 8 + tig * 2;
                *reinterpret_cast<__half2*>(&Cs[row0 * CS_STRIDE + col]) =
                    __floats2half2_rn(c[mi][ni][0], c[mi][ni][1]);
                *reinterpret_cast<__half2*>(&Cs[(row0 + 8) * CS_STRIDE + col]) =
                    __floats2half2_rn(c[mi][ni][2], c[mi][ni][3]);
                csum_r[ni * 2]     += c[mi][ni][0] + c[mi][ni][2];
                csum_r[ni * 2 + 1] += c[mi][ni][1] + c[mi][ni][3];
                csq_r[ni * 2]      += c[mi][ni][0] * c[mi][ni][0] + c[mi][ni][2] * c[mi][ni][2];
                csq_r[ni * 2 + 1]  += c[mi][ni][1] * c[mi][ni][1] + c[mi][ni][3] * c[mi][ni][3];
            }
        }
        __syncwarp();
#pragma unroll
        for (int p = 0; p < 8; p++) {
            int rl = wm * 64 + p * 8 + (lane >> 2);
            int seg = lane & 3;
            int m = mb * 128 + rl;
            if (m < NE) {
                *reinterpret_cast<uint4*>(raw_row(m) + n0 + wn * 32 + seg * 8) =
                    *reinterpret_cast<const uint4*>(&Cs[rl * CS_STRIDE + wn * 32 + seg * 8]);
            }
        }
        buf ^= 1;
    }

    __syncthreads();
#pragma unroll
    for (int ni = 0; ni < 4; ni++) {
#pragma unroll
        for (int t = 0; t < 2; t++) {
            int col = wn * 32 + ni * 8 + tig * 2 + t;
            atomicAdd(&csum_s[col], csum_r[ni * 2 + t]);
            atomicAdd(&csq_s[col],  csq_r[ni * 2 + t]);
        }
    }
    __syncthreads();
    if (tid < 128) {
        atomicAdd(&g_colsum[n0 + tid], csum_s[tid]);
        atomicAdd(&g_colsq[n0 + tid],  csq_s[tid]);
    }
}

// ---------------- BN coefficients ----------------
__global__ void k_bncoef(const float* __restrict__ gamma, const float* __restrict__ beta) {
    int i = blockIdx.x * 256 + threadIdx.x;
    if (i < DD) {
        float mu  = g_colsum[i] * (1.0f / NE);
        float var = g_colsq[i] * (1.0f / NE) - mu * mu;
        float a = gamma[i] * rsqrtf(var + EPSV);
        g_a[i] = a;
        g_c[i] = beta[i] - mu * a;
    }
}

// ---------------- message + scatter: agg[dst] += x[src] . (a*raw + c) -------------
// v3: warp-per-EDGE-PAIR; x broadcast via shfl (no smem staging, no syncwarp);
// 16B raw loads for both edges interleaved (MLP ~2x); a/c packed half2 in SMEM.
#define ACS 36   // half2 stride per d-row (32 + 4 pad)
__global__ __launch_bounds__(256) void k_msg(const float* __restrict__ x0,
                                             const int* __restrict__ ei,
                                             int first) {
    __shared__ __align__(16) __half2 a2_s[64 * ACS];
    __shared__ __align__(16) __half2 c2_s[64 * ACS];

    const float* __restrict__ x = first ? x0 : (const float*)g_node;
    int tid = threadIdx.x;
    for (int i = tid; i < 2048; i += 256) {
        int d = i >> 5, cc = i & 31;
        float2 av = *reinterpret_cast<const float2*>(&g_a[d * 64 + cc * 2]);
        float2 cv = *reinterpret_cast<const float2*>(&g_c[d * 64 + cc * 2]);
        a2_s[d * ACS + cc] = __floats2half2_rn(av.x, av.y);
        c2_s[d * ACS + cc] = __floats2half2_rn(cv.x, cv.y);
    }
    __syncthreads();

    int warp = tid >> 5, lane = tid & 31;
    int cq = lane & 7, dr = lane >> 3;
    int gp = blockIdx.x * 8 + warp;      // pair index; NE even -> no remainder edge

    for (int p = gp; p * 2 < NE; p += gridDim.x * 8) {
        int e0 = p * 2, e1 = e0 + 1;
        int s0 = ei[e0], d0 = ei[NE + e0];
        int s1 = ei[e1], d1 = ei[NE + e1];
        // per-lane x values; broadcast later via shfl
        float xlo0 = x[s0 * D + lane], xhi0 = x[s0 * D + 32 + lane];
        float xlo1 = x[s1 * D + lane], xhi1 = x[s1 * D + 32 + lane];

        const __half* r0 = raw_row(e0);
        const __half* r1 = raw_row(e1);
        float acc0[8], acc1[8];
#pragma unroll
        for (int j = 0; j < 8; j++) { acc0[j] = 0.f; acc1[j] = 0.f; }

#pragma unroll
        for (int it = 0; it < 16; it++) {
            int d = it * 4 + dr;
            uint4 rv0 = *reinterpret_cast<const uint4*>(r0 + d * D + cq * 8);
            uint4 rv1 = *reinterpret_cast<const uint4*>(r1 + d * D + cq * 8);
            uint4 av = *reinterpret_cast<const uint4*>(&a2_s[d * ACS + cq * 4]);
            uint4 cv = *reinterpret_cast<const uint4*>(&c2_s[d * ACS + cq * 4]);
            int sl = (it * 4 + dr) & 31;                    // shfl source lane
            float xv0 = (it < 8) ? __shfl_sync(0xffffffffu, xlo0, sl)
                                 : __shfl_sync(0xffffffffu, xhi0, sl);
            float xv1 = (it < 8) ? __shfl_sync(0xffffffffu, xlo1, sl)
                                 : __shfl_sync(0xffffffffu, xhi1, sl);
            const __half2* rh0 = reinterpret_cast<const __half2*>(&rv0);
            const __half2* rh1 = reinterpret_cast<const __half2*>(&rv1);
            const __half2* ah = reinterpret_cast<const __half2*>(&av);
            const __half2* ch = reinterpret_cast<const __half2*>(&cv);
#pragma unroll
            for (int q = 0; q < 4; q++) {
                __half2 m0 = __hfma2(ah[q], rh0[q], ch[q]);
                __half2 m1 = __hfma2(ah[q], rh1[q], ch[q]);
                float2 f0 = __half22float2(m0);
                float2 f1 = __half22float2(m1);
                acc0[q * 2]     = fmaf(xv0, f0.x, acc0[q * 2]);
                acc0[q * 2 + 1] = fmaf(xv0, f0.y, acc0[q * 2 + 1]);
                acc1[q * 2]     = fmaf(xv1, f1.x, acc1[q * 2]);
                acc1[q * 2 + 1] = fmaf(xv1, f1.y, acc1[q * 2 + 1]);
            }
        }
#pragma unroll
        for (int j = 0; j < 8; j++) {
            acc0[j] += __shfl_down_sync(0xffffffffu, acc0[j], 16);
            acc0[j] += __shfl_down_sync(0xffffffffu, acc0[j], 8);
            acc1[j] += __shfl_down_sync(0xffffffffu, acc1[j], 16);
            acc1[j] += __shfl_down_sync(0xffffffffu, acc1[j], 8);
        }
        if (lane < 8) {
            float* gp0 = &g_agg[d0 * D + lane * 8];
            float* gp1 = &g_agg[d1 * D + lane * 8];
#pragma unroll
            for (int j = 0; j < 8; j++) atomicAdd(gp0 + j, acc0[j]);
#pragma unroll
            for (int j = 0; j < 8; j++) atomicAdd(gp1 + j, acc1[j]);
        }
    }
}

// ---------------- fused GRU: xin inline + GEMVs in SMEM + gates + acc/out ---------
#define GRU_SMEM (2048 * 4 * 2 + 32 * 192 * 4 * 2)   // 65536 B
__global__ __launch_bounds__(192) void k_gru(const float* __restrict__ x0,
                                             const float* __restrict__ Wih,
                                             const float* __restrict__ Whh,
                                             const float* __restrict__ b_ih,
                                             const float* __restrict__ b_hh,
                                             const float* __restrict__ bias,
                                             float* __restrict__ out,
                                             int first, int last) {
    extern __shared__ __align__(16) unsigned char smg[];
    float* xs   = (float*)smg;
    float* hs   = xs + 2048;
    float* gi_s = hs + 2048;
    float* gh_s = gi_s + 32 * 192;

    const float* __restrict__ h = first ? x0 : (const float*)g_node;
    int tid = threadIdx.x;
    int base = blockIdx.x * 32;

    for (int f4 = tid; f4 < 512; f4 += 192) {
        int nb = base + (f4 >> 4);
        int c4 = (f4 & 15) * 4;
        float4 v = make_float4(0.f, 0.f, 0.f, 0.f), w = v;
        if (nb < NN) {
            float4 ag = *reinterpret_cast<const float4*>(&g_agg[nb * D + c4]);
            float iv = g_inv[nb];
            v.x = fmaxf(fmaf(ag.x, iv, bias[c4 + 0]), 0.f);
            v.y = fmaxf(fmaf(ag.y, iv, bias[c4 + 1]), 0.f);
            v.z = fmaxf(fmaf(ag.z, iv, bias[c4 + 2]), 0.f);
            v.w = fmaxf(fmaf(ag.w, iv, bias[c4 + 3]), 0.f);
            *reinterpret_cast<float4*>(&g_agg[nb * D + c4]) = make_float4(0.f, 0.f, 0.f, 0.f);
            w = *reinterpret_cast<const float4*>(&h[nb * D + c4]);
        }
        *reinterpret_cast<float4*>(&xs[f4 * 4]) = v;
        *reinterpret_cast<float4*>(&hs[f4 * 4]) = w;
    }
    __syncthreads();

    {
        float4 wr[16];
#pragma unroll
        for (int q = 0; q < 16; q++) wr[q] = reinterpret_cast<const float4*>(Wih)[tid * 16 + q];
        for (int nn = 0; nn < 32; nn++) {
            float acc = 0.f;
#pragma unroll
            for (int q = 0; q < 16; q++) {
                float4 xv = *reinterpret_cast<float4*>(&xs[nn * D + q * 4]);
                float4 wv = wr[q];
                acc = fmaf(xv.x, wv.x, acc); acc = fmaf(xv.y, wv.y, acc);
                acc = fmaf(xv.z, wv.z, acc); acc = fmaf(xv.w, wv.w, acc);
            }
            gi_s[nn * 192 + tid] = acc;
        }
#pragma unroll
        for (int q = 0; q < 16; q++) wr[q] = reinterpret_cast<const float4*>(Whh)[tid * 16 + q];
        for (int nn = 0; nn < 32; nn++) {
            float acc = 0.f;
#pragma unroll
            for (int q = 0; q < 16; q++) {
                float4 xv = *reinterpret_cast<float4*>(&hs[nn * D + q * 4]);
                float4 wv = wr[q];
                acc = fmaf(xv.x, wv.x, acc); acc = fmaf(xv.y, wv.y, acc);
                acc = fmaf(xv.z, wv.z, acc); acc = fmaf(xv.w, wv.w, acc);
            }
            gh_s[nn * 192 + tid] = acc;
        }
    }
    __syncthreads();

    for (int i = tid; i < 2048; i += 192) {
        int gidx = base * D + i;
        if (gidx >= NN * D) break;
        int nl = i >> 6, j = i & 63;

        float ir = gi_s[nl * 192 + j]       + b_ih[j];
        float iz = gi_s[nl * 192 + 64 + j]  + b_ih[64 + j];
        float in = gi_s[nl * 192 + 128 + j] + b_ih[128 + j];
        float hr = gh_s[nl * 192 + j]       + b_hh[j];
        float hz = gh_s[nl * 192 + 64 + j]  + b_hh[64 + j];
        float hn = gh_s[nl * 192 + 128 + j] + b_hh[128 + j];

        float r = 1.0f / (1.0f + expf(-(ir + hr)));
        float z = 1.0f / (1.0f + expf(-(iz + hz)));
        float nv = tanhf(fmaf(r, hn, in));

        float hold = hs[i];
        float hnew = fmaf(z, hold - nv, nv);   // (1-z)*n + z*h

        if (last) {
            out[gidx] = (g_acc[gidx] + hold + hnew) * 0.25f + x0[gidx];
        } else {
            if (first) g_acc[gidx] = hold;
            else       g_acc[gidx] += hold;
            g_node[gidx] = hnew;
        }
    }
}

// ---------------- launcher ----------------
extern "C" void kernel_launch(void* const* d_in, const int* in_sizes, int n_in,
                              void* d_out, int out_size) {
    const float* node   = (const float*)d_in[0];
    const int*   ei     = (const int*)d_in[1];     // int32 (JAX x64 disabled)
    const float* edge   = (const float*)d_in[2];
    const float* W_edge = (const float*)d_in[3];
    const float* gamma  = (const float*)d_in[4];
    const float* beta   = (const float*)d_in[5];
    const float* bias   = (const float*)d_in[6];
    const float* W_ih   = (const float*)d_in[7];
    const float* W_hh   = (const float*)d_in[8];
    const float* b_ih   = (const float*)d_in[9];
    const float* b_hh   = (const float*)d_in[10];
    float* out = (float*)d_out;

    cudaFuncSetAttribute(k_gemm_edge, cudaFuncAttributeMaxDynamicSharedMemorySize, GEMM_SMEM);
    cudaFuncSetAttribute(k_gru, cudaFuncAttributeMaxDynamicSharedMemorySize, GRU_SMEM);

    int nelem_blocks = (NN * D + 255) / 256;
    k_zero_pre<<<nelem_blocks, 256>>>();
    k_count<<<(NE + 255) / 256, 256>>>(ei);
    k_inv<<<196, 256>>>();

    k_toh_A<<<(NEPAD * F / 8 + 255) / 256, 256>>>(edge);
    k_toh_B<<<(F * DD / 8 + 255) / 256, 256>>>(W_edge);

    dim3 gg(DD / 128, GY);
    k_gemm_edge<<<gg, 256, GEMM_SMEM>>>();
    k_bncoef<<<16, 256>>>(gamma, beta);

    // only 3 propagation steps needed: out = x0 + mean(node_0..node_3);
    // the reference's 4th GRU update is dead code.
    for (int s = 0; s < 3; s++) {
        int first = (s == 0) ? 1 : 0;
        int last = (s == 2) ? 1 : 0;
        k_msg<<<1184, 256>>>(node, ei, first);
        k_gru<<<(NN + 31) / 32, 192, GRU_SMEM>>>(node, W_ih, W_hh, b_ih, b_hh, bias, out, first, last);
    }
}